// round 8
// baseline (speedup 1.0000x reference)
#include <cuda_runtime.h>
#include <cuda_bf16.h>
#include <math.h>

// Problem constants
#define NN_ 16384
#define MM_ 8192
#define DD_ 512
#define FF_ 2048

// ---------------- static scratch (no runtime allocation allowed) ----------------
__device__ float g_anorm[MM_];
__device__ float g_S[(size_t)NN_ * MM_];          // 512 MB: coarse src @ anchor^T
__device__ __nv_bfloat16 g_src_bf[(size_t)NN_ * DD_];
__device__ __nv_bfloat16 g_anch_bf[(size_t)MM_ * DD_];

// split activations (hi/lo bf16)
__device__ __nv_bfloat16 g_neigh_hi[(size_t)NN_ * DD_];
__device__ __nv_bfloat16 g_neigh_lo[(size_t)NN_ * DD_];
__device__ __nv_bfloat16 g_cat_hi[(size_t)NN_ * 2 * DD_];
__device__ __nv_bfloat16 g_cat_lo[(size_t)NN_ * 2 * DD_];
__device__ __nv_bfloat16 g_combn_hi[(size_t)NN_ * DD_];
__device__ __nv_bfloat16 g_combn_lo[(size_t)NN_ * DD_];
__device__ __nv_bfloat16 g_h_hi[(size_t)NN_ * FF_];
__device__ __nv_bfloat16 g_h_lo[(size_t)NN_ * FF_];
__device__ __nv_bfloat16 g_c2_hi[(size_t)NN_ * DD_];
__device__ __nv_bfloat16 g_c2_lo[(size_t)NN_ * DD_];

// fp32 intermediates
__device__ float g_comb[(size_t)NN_ * DD_];
__device__ float g_combn[(size_t)NN_ * DD_];      // fp32 kept for residual add
__device__ float g_r[(size_t)NN_ * DD_];
__device__ float g_dec[(size_t)NN_ * DD_];

// transposed + split weights (Wt[n][k] = W[k][n])
__device__ __nv_bfloat16 g_WdimT_hi[DD_ * DD_];
__device__ __nv_bfloat16 g_WdimT_lo[DD_ * DD_];
__device__ __nv_bfloat16 g_WfusT_hi[DD_ * 2 * DD_];
__device__ __nv_bfloat16 g_WfusT_lo[DD_ * 2 * DD_];
__device__ __nv_bfloat16 g_We1T_hi[(size_t)FF_ * DD_];
__device__ __nv_bfloat16 g_We1T_lo[(size_t)FF_ * DD_];
__device__ __nv_bfloat16 g_We2T_hi[(size_t)DD_ * FF_];
__device__ __nv_bfloat16 g_We2T_lo[(size_t)DD_ * FF_];
__device__ __nv_bfloat16 g_WdT_hi[DD_ * DD_];
__device__ __nv_bfloat16 g_WdT_lo[DD_ * DD_];

// BN
__device__ float g_part[2 * 128 * DD_];
__device__ float g_scale[DD_];
__device__ float g_shift[DD_];

// ---------------- helpers ----------------
__device__ __forceinline__ void split2(float x, float y,
                                       __nv_bfloat162& hi, __nv_bfloat162& lo) {
    hi = __floats2bfloat162_rn(x, y);
    float rx = x - __bfloat162float(hi.x);
    float ry = y - __bfloat162float(hi.y);
    lo = __floats2bfloat162_rn(rx, ry);
}

// ---------------- fp32 -> bf16 conversion (single, for distance GEMM) ----------------
__global__ void tobf16_kernel(const float* __restrict__ X, __nv_bfloat16* __restrict__ Y) {
    size_t i = ((size_t)blockIdx.x * 256 + threadIdx.x) * 4;
    float4 x = *reinterpret_cast<const float4*>(X + i);
    __nv_bfloat162 lo = __floats2bfloat162_rn(x.x, x.y);
    __nv_bfloat162 hi = __floats2bfloat162_rn(x.z, x.w);
    uint2 p;
    p.x = *reinterpret_cast<unsigned*>(&lo);
    p.y = *reinterpret_cast<unsigned*>(&hi);
    *reinterpret_cast<uint2*>(Y + i) = p;
}

// ---------------- src -> split bf16 into left half of concat ----------------
__global__ void pack_split_kernel(const float* __restrict__ src) {
    size_t i = ((size_t)blockIdx.x * 256 + threadIdx.x) * 4;   // over NN_*DD_
    size_t r = i >> 9;
    int c = (int)(i & 511);
    float4 x = *reinterpret_cast<const float4*>(src + i);
    __nv_bfloat162 h0, l0, h1, l1;
    split2(x.x, x.y, h0, l0);
    split2(x.z, x.w, h1, l1);
    uint2 ph, pl;
    ph.x = *reinterpret_cast<unsigned*>(&h0); ph.y = *reinterpret_cast<unsigned*>(&h1);
    pl.x = *reinterpret_cast<unsigned*>(&l0); pl.y = *reinterpret_cast<unsigned*>(&l1);
    *reinterpret_cast<uint2*>(g_cat_hi + r * 1024 + c) = ph;
    *reinterpret_cast<uint2*>(g_cat_lo + r * 1024 + c) = pl;
}

// ---------------- weight transpose + split: Thi/Tlo[n][k] = split(W[k][n]) ----------------
__global__ void tsplit_kernel(const float* __restrict__ W,
                              __nv_bfloat16* __restrict__ Thi,
                              __nv_bfloat16* __restrict__ Tlo, int K, int N) {
    __shared__ float tile[32][33];
    int n0 = blockIdx.x * 32, k0 = blockIdx.y * 32;
    int tx = threadIdx.x, ty = threadIdx.y;
    #pragma unroll
    for (int i = 0; i < 4; i++)
        tile[ty + i * 8][tx] = W[(size_t)(k0 + ty + i * 8) * N + n0 + tx];
    __syncthreads();
    #pragma unroll
    for (int i = 0; i < 4; i++) {
        int n = n0 + ty + i * 8;
        float v = tile[tx][ty + i * 8];
        __nv_bfloat16 h = __float2bfloat16(v);
        __nv_bfloat16 l = __float2bfloat16(v - __bfloat162float(h));
        Thi[(size_t)n * K + k0 + tx] = h;
        Tlo[(size_t)n * K + k0 + tx] = l;
    }
}

// ---------------- anchor squared norms ----------------
__global__ void anorm_kernel(const float* __restrict__ A) {
    int warp = threadIdx.x >> 5, lane = threadIdx.x & 31;
    int row = blockIdx.x * 8 + warp;
    const float* p = A + (size_t)row * DD_;
    float s = 0.f;
    for (int c = lane; c < DD_; c += 32) { float v = p[c]; s += v * v; }
    #pragma unroll
    for (int o = 16; o; o >>= 1) s += __shfl_xor_sync(0xffffffffu, s, o);
    if (lane == 0) g_anorm[row] = s;
}

// ---------------- bf16 tensor-core GEMM (NT), multi-pass hi/lo ----------------
// NPASS==1: C = Ahi * Bhi^T
// NPASS==3: C = Ahi*Bhi^T + Alo*Bhi^T + Ahi*Blo^T   (fp32-accurate split product)
// EPI: 0 = fp32 store, 1 = +bias fp32, 2 = +bias tanh -> split bf16,
//      3 = +bias +res fp32, 4 = +bias -> split bf16
#define LDS_BF 40

template <int NPASS, int EPI>
__global__ __launch_bounds__(256) void gemm_bf16_mp(
    const __nv_bfloat16* __restrict__ Ahi, const __nv_bfloat16* __restrict__ Alo,
    const __nv_bfloat16* __restrict__ Bhi, const __nv_bfloat16* __restrict__ Blo,
    const float* __restrict__ bias, const float* __restrict__ res,
    float* __restrict__ C, __nv_bfloat16* __restrict__ Chi,
    __nv_bfloat16* __restrict__ Clo,
    int K, int lda, int ldb, int ldc)
{
    __shared__ __nv_bfloat16 As[2][128 * LDS_BF];
    __shared__ __nv_bfloat16 Bs[2][128 * LDS_BF];
    const int tid = threadIdx.x;
    const int lane = tid & 31, w = tid >> 5;
    const int wr = w >> 2, wc = w & 3;
    const int rowBase = blockIdx.y * 128;
    const int colBase = blockIdx.x * 128;

    float acc[4][4][4];
    #pragma unroll
    for (int i = 0; i < 4; i++)
        #pragma unroll
        for (int j = 0; j < 4; j++)
            #pragma unroll
            for (int k = 0; k < 4; k++) acc[i][j][k] = 0.f;

    const int KT = K / 32;
    const int TT = NPASS * KT;

    #define ISSUE_TILE(t, buf)                                                     \
    {                                                                              \
        int p_ = (t) / KT;                                                         \
        int k0 = ((t) - p_ * KT) * 32;                                             \
        const __nv_bfloat16* Ab = (NPASS == 3 && p_ == 1) ? Alo : Ahi;             \
        const __nv_bfloat16* Bb = (NPASS == 3 && p_ == 2) ? Blo : Bhi;             \
        _Pragma("unroll")                                                          \
        for (int i = 0; i < 2; i++) {                                              \
            int v = tid + i * 256;                                                 \
            int r = v >> 2, c8 = (v & 3) * 8;                                      \
            unsigned sa = (unsigned)__cvta_generic_to_shared(                      \
                &As[buf][r * LDS_BF + c8]);                                        \
            const __nv_bfloat16* ga = Ab + (size_t)(rowBase + r) * lda + k0 + c8;  \
            asm volatile("cp.async.ca.shared.global [%0], [%1], 16;\n"             \
                         :: "r"(sa), "l"(ga));                                     \
            unsigned sb = (unsigned)__cvta_generic_to_shared(                      \
                &Bs[buf][r * LDS_BF + c8]);                                        \
            const __nv_bfloat16* gb = Bb + (size_t)(colBase + r) * ldb + k0 + c8;  \
            asm volatile("cp.async.ca.shared.global [%0], [%1], 16;\n"             \
                         :: "r"(sb), "l"(gb));                                     \
        }                                                                          \
        asm volatile("cp.async.commit_group;\n");                                  \
    }

    ISSUE_TILE(0, 0);

    for (int t = 0; t < TT; t++) {
        int buf = t & 1;
        if (t + 1 < TT) { ISSUE_TILE(t + 1, buf ^ 1); }
        else            { asm volatile("cp.async.commit_group;\n"); }
        asm volatile("cp.async.wait_group 1;\n");
        __syncthreads();

        #pragma unroll
        for (int ks = 0; ks < 2; ks++) {
            unsigned a[4][4], b[4][2];
            #pragma unroll
            for (int mt = 0; mt < 4; mt++) {
                int r = wr * 64 + mt * 16 + (lane & 15);
                int c = ks * 16 + (lane >> 4) * 8;
                unsigned addr = (unsigned)__cvta_generic_to_shared(
                    &As[buf][r * LDS_BF + c]);
                asm volatile(
                    "ldmatrix.sync.aligned.m8n8.x4.shared.b16 {%0,%1,%2,%3}, [%4];\n"
                    : "=r"(a[mt][0]), "=r"(a[mt][1]), "=r"(a[mt][2]), "=r"(a[mt][3])
                    : "r"(addr));
            }
            #pragma unroll
            for (int nt = 0; nt < 4; nt++) {
                int r = wc * 32 + nt * 8 + (lane & 7);
                int c = ks * 16 + ((lane >> 3) & 1) * 8;
                unsigned addr = (unsigned)__cvta_generic_to_shared(
                    &Bs[buf][r * LDS_BF + c]);
                asm volatile(
                    "ldmatrix.sync.aligned.m8n8.x2.shared.b16 {%0,%1}, [%2];\n"
                    : "=r"(b[nt][0]), "=r"(b[nt][1]) : "r"(addr));
            }
            #pragma unroll
            for (int mt = 0; mt < 4; mt++)
                #pragma unroll
                for (int nt = 0; nt < 4; nt++) {
                    float* c = acc[mt][nt];
                    asm volatile(
                        "mma.sync.aligned.m16n8k16.row.col.f32.bf16.bf16.f32 "
                        "{%0,%1,%2,%3}, {%4,%5,%6,%7}, {%8,%9}, {%0,%1,%2,%3};\n"
                        : "+f"(c[0]), "+f"(c[1]), "+f"(c[2]), "+f"(c[3])
                        : "r"(a[mt][0]), "r"(a[mt][1]), "r"(a[mt][2]), "r"(a[mt][3]),
                          "r"(b[nt][0]), "r"(b[nt][1]));
                }
        }
        __syncthreads();
    }
    #undef ISSUE_TILE

    // epilogue
    #pragma unroll
    for (int mt = 0; mt < 4; mt++) {
        int row0 = rowBase + wr * 64 + mt * 16 + (lane >> 2);
        #pragma unroll
        for (int nt = 0; nt < 4; nt++) {
            int col = colBase + wc * 32 + nt * 8 + (lane & 3) * 2;
            #pragma unroll
            for (int half = 0; half < 2; half++) {
                int row = row0 + half * 8;
                float vx = acc[mt][nt][half * 2 + 0];
                float vy = acc[mt][nt][half * 2 + 1];
                if (EPI >= 1) { vx += bias[col]; vy += bias[col + 1]; }
                if (EPI == 2) { vx = tanhf(vx); vy = tanhf(vy); }
                if (EPI == 3) {
                    const float2 rr = *reinterpret_cast<const float2*>(
                        res + (size_t)row * ldc + col);
                    vx += rr.x; vy += rr.y;
                }
                if (EPI == 2 || EPI == 4) {
                    __nv_bfloat162 h2, l2;
                    split2(vx, vy, h2, l2);
                    *reinterpret_cast<unsigned*>(Chi + (size_t)row * ldc + col) =
                        *reinterpret_cast<unsigned*>(&h2);
                    *reinterpret_cast<unsigned*>(Clo + (size_t)row * ldc + col) =
                        *reinterpret_cast<unsigned*>(&l2);
                } else {
                    *reinterpret_cast<float2*>(C + (size_t)row * ldc + col) =
                        make_float2(vx, vy);
                }
            }
        }
    }
}

// ---------------- coarse top-16 (merge tree) -> exact fp32 rescore -> top-5 + mean ----------------
// Phase 1: per-thread sorted top-16 over 32 elements (float4 loads).
// Phase 2: binary merge tree over 256 sorted lists in smem (8 levels, 1 sync each).
// Exactness: lexicographic (value, index) ordering preserved at every merge.
__global__ __launch_bounds__(256) void topk16_kernel(
    const float* __restrict__ src, const float* __restrict__ anchors)
{
    int n = blockIdx.x;
    int tid = threadIdx.x;
    int lane = tid & 31, w = tid >> 5;
    const float* Srow = g_S + (size_t)n * MM_;

    float v[16]; int id[16];
    #pragma unroll
    for (int i = 0; i < 16; i++) { v[i] = 3.4e38f; id[i] = 0x7fffffff; }

    // each thread: 8 float4 = 32 contiguous-by-stride elements
    #pragma unroll
    for (int q = 0; q < 8; q++) {
        int m0 = q * 1024 + tid * 4;
        float4 s4 = *reinterpret_cast<const float4*>(Srow + m0);
        float4 a4 = *reinterpret_cast<const float4*>(g_anorm + m0);
        float dv[4] = { a4.x - 2.0f * s4.x, a4.y - 2.0f * s4.y,
                        a4.z - 2.0f * s4.z, a4.w - 2.0f * s4.w };
        #pragma unroll
        for (int u = 0; u < 4; u++) {
            float d = dv[u]; int m = m0 + u;
            if (d < v[15] || (d == v[15] && m < id[15])) {
                int p = 15;
                while (p > 0 && (d < v[p-1] || (d == v[p-1] && m < id[p-1]))) {
                    v[p] = v[p-1]; id[p] = id[p-1]; p--;
                }
                v[p] = d; id[p] = m;
            }
        }
    }

    __shared__ float sv[256 * 16 + 16];
    __shared__ int   si[256 * 16 + 16];
    #pragma unroll
    for (int i = 0; i < 16; i++) { sv[tid * 16 + i] = v[i]; si[tid * 16 + i] = id[i]; }
    __syncthreads();

    // merge tree: 8 levels; level with `pairs` merges keeps lists at stride 2*width
    #pragma unroll
    for (int width = 1; width < 256; width <<= 1) {
        int pairs = 128 / width;
        if (tid < pairs) {
            int aBase = (tid * 2 * width) * 16;
            int bBase = aBase + width * 16;
            float rv[16]; int ri[16];
            int i = 0, j = 0;
            float av = sv[aBase], bv = sv[bBase];
            int ai = si[aBase], bi = si[bBase];
            #pragma unroll
            for (int k = 0; k < 16; k++) {
                bool takeA = (av < bv) || (av == bv && ai < bi);
                if (takeA) {
                    rv[k] = av; ri[k] = ai; i++;
                    av = sv[aBase + i]; ai = si[aBase + i];
                } else {
                    rv[k] = bv; ri[k] = bi; j++;
                    bv = sv[bBase + j]; bi = si[bBase + j];
                }
            }
            #pragma unroll
            for (int k = 0; k < 16; k++) { sv[aBase + k] = rv[k]; si[aBase + k] = ri[k]; }
        }
        __syncthreads();
    }
    // sv[0..15] / si[0..15] = exact coarse top-16

    // exact fp32 rescore of 16 candidates (8 warps x 2 candidates)
    __shared__ float dex[16];
    const float* srow = src + (size_t)n * DD_;
    for (int c = w; c < 16; c += 8) {
        int m = si[c];
        const float* a = anchors + (size_t)m * DD_;
        float s = 0.f;
        for (int i = lane; i < DD_; i += 32) s += srow[i] * a[i];
        #pragma unroll
        for (int o = 16; o; o >>= 1) s += __shfl_xor_sync(0xffffffffu, s, o);
        if (lane == 0) dex[c] = g_anorm[m] - 2.0f * s;
    }
    __syncthreads();

    __shared__ int win5[5];
    if (tid == 0) {
        bool used[16];
        #pragma unroll
        for (int i = 0; i < 16; i++) used[i] = false;
        for (int r2 = 0; r2 < 5; r2++) {
            float bv = 3.4e38f; int bi = 0x7fffffff; int bc = 0;
            for (int c = 0; c < 16; c++) {
                if (used[c]) continue;
                if (dex[c] < bv || (dex[c] == bv && si[c] < bi)) {
                    bv = dex[c]; bi = si[c]; bc = c;
                }
            }
            used[bc] = true; win5[r2] = bi;
        }
    }
    __syncthreads();

    // neigh mean -> split bf16
    for (int c = tid; c < DD_; c += 256) {
        float s = 0.f;
        #pragma unroll
        for (int k = 0; k < 5; k++) s += anchors[(size_t)win5[k] * DD_ + c];
        float m = s * 0.2f;
        __nv_bfloat16 h = __float2bfloat16(m);
        __nv_bfloat16 l = __float2bfloat16(m - __bfloat162float(h));
        g_neigh_hi[(size_t)n * DD_ + c] = h;
        g_neigh_lo[(size_t)n * DD_ + c] = l;
    }
}

// ---------------- BN: deterministic two-stage column stats ----------------
__global__ __launch_bounds__(256) void bn_stats_kernel(const float* __restrict__ X) {
    int b = blockIdx.x;
    int c0 = threadIdx.x, c1 = threadIdx.x + 256;
    float s0 = 0, q0 = 0, s1 = 0, q1 = 0;
    const float* p = X + (size_t)b * 128 * DD_;
    for (int r = 0; r < 128; r++) {
        float x0 = p[(size_t)r * DD_ + c0];
        float x1 = p[(size_t)r * DD_ + c1];
        s0 += x0; q0 += x0 * x0;
        s1 += x1; q1 += x1 * x1;
    }
    g_part[b * DD_ + c0] = s0;
    g_part[b * DD_ + c1] = s1;
    g_part[128 * DD_ + b * DD_ + c0] = q0;
    g_part[128 * DD_ + b * DD_ + c1] = q1;
}

__global__ void bn_finalize_kernel(const float* __restrict__ g,
                                   const float* __restrict__ bt) {
    int c = blockIdx.x * 256 + threadIdx.x;
    float s = 0, q = 0;
    for (int b = 0; b < 128; b++) {
        s += g_part[b * DD_ + c];
        q += g_part[128 * DD_ + b * DD_ + c];
    }
    float mu = s * (1.0f / NN_);
    float var = q * (1.0f / NN_) - mu * mu;
    float sc = g[c] * rsqrtf(var + 1e-5f);
    g_scale[c] = sc;
    g_shift[c] = bt[c] - mu * sc;
}

// BN apply; SPLIT: also emit hi/lo bf16 (same linear layout, ld=512)
template <bool TANH, bool SPLIT>
__global__ void bn_apply_kernel(const float* __restrict__ X, float* __restrict__ Y,
                                __nv_bfloat16* __restrict__ Yhi,
                                __nv_bfloat16* __restrict__ Ylo) {
    size_t i = ((size_t)blockIdx.x * 256 + threadIdx.x) * 4;
    int c = (int)(i & (DD_ - 1));
    float4 x  = *reinterpret_cast<const float4*>(X + i);
    float4 sc = *reinterpret_cast<const float4*>(g_scale + c);
    float4 sh = *reinterpret_cast<const float4*>(g_shift + c);
    float4 y;
    y.x = x.x * sc.x + sh.x; y.y = x.y * sc.y + sh.y;
    y.z = x.z * sc.z + sh.z; y.w = x.w * sc.w + sh.w;
    if (TANH) { y.x = tanhf(y.x); y.y = tanhf(y.y); y.z = tanhf(y.z); y.w = tanhf(y.w); }
    *reinterpret_cast<float4*>(Y + i) = y;
    if (SPLIT) {
        __nv_bfloat162 h0, l0, h1, l1;
        split2(y.x, y.y, h0, l0);
        split2(y.z, y.w, h1, l1);
        uint2 ph, pl;
        ph.x = *reinterpret_cast<unsigned*>(&h0); ph.y = *reinterpret_cast<unsigned*>(&h1);
        pl.x = *reinterpret_cast<unsigned*>(&l0); pl.y = *reinterpret_cast<unsigned*>(&l1);
        *reinterpret_cast<uint2*>(Yhi + i) = ph;
        *reinterpret_cast<uint2*>(Ylo + i) = pl;
    }
}

// ---------------- launch ----------------
static float* symAddr(const void* symbol) {
    void* p = nullptr;
    cudaGetSymbolAddress(&p, symbol);
    return (float*)p;
}

extern "C" void kernel_launch(void* const* d_in, const int* in_sizes, int n_in,
                              void* d_out, int out_size) {
    (void)in_sizes; (void)n_in; (void)out_size;
    const float* src    = (const float*)d_in[0];
    const float* anchor = (const float*)d_in[1];
    const float* W_dim  = (const float*)d_in[2];
    const float* b_dim  = (const float*)d_in[3];
    const float* W_fus  = (const float*)d_in[4];
    const float* b_fus  = (const float*)d_in[5];
    const float* W_e1   = (const float*)d_in[6];
    const float* b_e1   = (const float*)d_in[7];
    const float* W_e2   = (const float*)d_in[8];
    const float* b_e2   = (const float*)d_in[9];
    const float* g1     = (const float*)d_in[10];
    const float* bt1    = (const float*)d_in[11];
    const float* g2     = (const float*)d_in[12];
    const float* bt2    = (const float*)d_in[13];
    const float* W_d    = (const float*)d_in[14];
    const float* b_d    = (const float*)d_in[15];
    const float* g_d    = (const float*)d_in[16];
    const float* bt_d   = (const float*)d_in[17];
    float* out = (float*)d_out;

    float* pS      = symAddr(g_S);
    float* pComb   = symAddr(g_comb);
    float* pCombn  = symAddr(g_combn);
    float* pR      = symAddr(g_r);
    float* pDec    = symAddr(g_dec);
    __nv_bfloat16* pSrcBf   = (__nv_bfloat16*)symAddr(g_src_bf);
    __nv_bfloat16* pAnchBf  = (__nv_bfloat16*)symAddr(g_anch_bf);
    __nv_bfloat16* pNeighH  = (__nv_bfloat16*)symAddr(g_neigh_hi);
    __nv_bfloat16* pNeighL  = (__nv_bfloat16*)symAddr(g_neigh_lo);
    __nv_bfloat16* pCatH    = (__nv_bfloat16*)symAddr(g_cat_hi);
    __nv_bfloat16* pCatL    = (__nv_bfloat16*)symAddr(g_cat_lo);
    __nv_bfloat16* pCombnH  = (__nv_bfloat16*)symAddr(g_combn_hi);
    __nv_bfloat16* pCombnL  = (__nv_bfloat16*)symAddr(g_combn_lo);
    __nv_bfloat16* pHH      = (__nv_bfloat16*)symAddr(g_h_hi);
    __nv_bfloat16* pHL      = (__nv_bfloat16*)symAddr(g_h_lo);
    __nv_bfloat16* pC2H     = (__nv_bfloat16*)symAddr(g_c2_hi);
    __nv_bfloat16* pC2L     = (__nv_bfloat16*)symAddr(g_c2_lo);
    __nv_bfloat16* pWdimH   = (__nv_bfloat16*)symAddr(g_WdimT_hi);
    __nv_bfloat16* pWdimL   = (__nv_bfloat16*)symAddr(g_WdimT_lo);
    __nv_bfloat16* pWfusH   = (__nv_bfloat16*)symAddr(g_WfusT_hi);
    __nv_bfloat16* pWfusL   = (__nv_bfloat16*)symAddr(g_WfusT_lo);
    __nv_bfloat16* pWe1H    = (__nv_bfloat16*)symAddr(g_We1T_hi);
    __nv_bfloat16* pWe1L    = (__nv_bfloat16*)symAddr(g_We1T_lo);
    __nv_bfloat16* pWe2H    = (__nv_bfloat16*)symAddr(g_We2T_hi);
    __nv_bfloat16* pWe2L    = (__nv_bfloat16*)symAddr(g_We2T_lo);
    __nv_bfloat16* pWdH     = (__nv_bfloat16*)symAddr(g_WdT_hi);
    __nv_bfloat16* pWdL     = (__nv_bfloat16*)symAddr(g_WdT_lo);

    const int T = 256;

    // 0) bf16 copies for the coarse distance GEMM + weight transpose/split
    tobf16_kernel<<<(NN_ * DD_ / 4) / T, T>>>(src, pSrcBf);
    tobf16_kernel<<<(MM_ * DD_ / 4) / T, T>>>(anchor, pAnchBf);
    tsplit_kernel<<<dim3(DD_ / 32, DD_ / 32), dim3(32, 8)>>>(W_dim, pWdimH, pWdimL, DD_, DD_);
    tsplit_kernel<<<dim3(DD_ / 32, 2 * DD_ / 32), dim3(32, 8)>>>(W_fus, pWfusH, pWfusL, 2 * DD_, DD_);
    tsplit_kernel<<<dim3(FF_ / 32, DD_ / 32), dim3(32, 8)>>>(W_e1, pWe1H, pWe1L, DD_, FF_);
    tsplit_kernel<<<dim3(DD_ / 32, FF_ / 32), dim3(32, 8)>>>(W_e2, pWe2H, pWe2L, FF_, DD_);
    tsplit_kernel<<<dim3(DD_ / 32, DD_ / 32), dim3(32, 8)>>>(W_d, pWdH, pWdL, DD_, DD_);

    // 1) anchor norms (fp32)
    anorm_kernel<<<MM_ / 8, T>>>(anchor);

    // 2) coarse S = src_bf @ anchor_bf^T (single-pass bf16)
    gemm_bf16_mp<1, 0><<<dim3(MM_ / 128, NN_ / 128), T>>>(
        pSrcBf, nullptr, pAnchBf, nullptr, nullptr, nullptr,
        pS, nullptr, nullptr, DD_, DD_, DD_, MM_);

    // 3) top-16 (merge tree) -> exact rescore -> top-5 -> neigh (split bf16)
    topk16_kernel<<<NN_, T>>>(src, anchor);

    // 4) cat left = split(src); cat right = neigh @ W_dim + b_dim (split epilogue)
    pack_split_kernel<<<(NN_ * DD_ / 4) / T, T>>>(src);
    gemm_bf16_mp<3, 4><<<dim3(DD_ / 128, NN_ / 128), T>>>(
        pNeighH, pNeighL, pWdimH, pWdimL, b_dim, nullptr,
        nullptr, pCatH + DD_, pCatL + DD_, DD_, DD_, DD_, 2 * DD_);

    // 5) comb = cat @ W_fus + b_fus (K=1024) -> fp32
    gemm_bf16_mp<3, 1><<<dim3(DD_ / 128, NN_ / 128), T>>>(
        pCatH, pCatL, pWfusH, pWfusL, b_fus, nullptr,
        pComb, nullptr, nullptr, 2 * DD_, 2 * DD_, 2 * DD_, DD_);

    // 6) BN1 -> combn fp32 + split bf16
    bn_stats_kernel<<<128, T>>>(pComb);
    bn_finalize_kernel<<<2, T>>>(g1, bt1);
    bn_apply_kernel<false, true><<<(NN_ * DD_ / 4) / T, T>>>(pComb, pCombn, pCombnH, pCombnL);

    // 7) h = tanh(combn @ W_e1 + b_e1) -> split bf16 directly (no fp32 h)
    gemm_bf16_mp<3, 2><<<dim3(FF_ / 128, NN_ / 128), T>>>(
        pCombnH, pCombnL, pWe1H, pWe1L, b_e1, nullptr,
        nullptr, pHH, pHL, DD_, DD_, DD_, FF_);

    // 8) r = combn + (h @ W_e2 + b_e2) (K=2048) -> fp32
    gemm_bf16_mp<3, 3><<<dim3(DD_ / 128, NN_ / 128), T>>>(
        pHH, pHL, pWe2H, pWe2L, b_e2, pCombn,
        pR, nullptr, nullptr, FF_, FF_, FF_, DD_);

    // 9) BN2 -> comb2 split bf16
    bn_stats_kernel<<<128, T>>>(pR);
    bn_finalize_kernel<<<2, T>>>(g2, bt2);
    bn_apply_kernel<false, true><<<(NN_ * DD_ / 4) / T, T>>>(pR, pComb, pC2H, pC2L);

    // 10) dec = comb2 @ W_d + b_d -> fp32
    gemm_bf16_mp<3, 1><<<dim3(DD_ / 128, NN_ / 128), T>>>(
        pC2H, pC2L, pWdH, pWdL, b_d, nullptr,
        pDec, nullptr, nullptr, DD_, DD_, DD_, DD_);

    // 11) out = tanh(BN(dec))
    bn_stats_kernel<<<128, T>>>(pDec);
    bn_finalize_kernel<<<2, T>>>(g_d, bt_d);
    bn_apply_kernel<true, false><<<(NN_ * DD_ / 4) / T, T>>>(pDec, out, nullptr, nullptr);
}

// round 12
// speedup vs baseline: 2.6001x; 2.6001x over previous
#include <cuda_runtime.h>
#include <cuda_bf16.h>
#include <math.h>

// Problem constants
#define NN_ 16384
#define MM_ 8192
#define DD_ 512
#define FF_ 2048

// ---------------- static scratch (no runtime allocation allowed) ----------------
__device__ float g_anorm[MM_];
__device__ float g_S[(size_t)NN_ * MM_];          // 512 MB: coarse src @ anchor^T
__device__ __nv_bfloat16 g_src_bf[(size_t)NN_ * DD_];
__device__ __nv_bfloat16 g_anch_bf[(size_t)MM_ * DD_];

// split activations (hi/lo bf16)
__device__ __nv_bfloat16 g_neigh_hi[(size_t)NN_ * DD_];
__device__ __nv_bfloat16 g_neigh_lo[(size_t)NN_ * DD_];
__device__ __nv_bfloat16 g_cat_hi[(size_t)NN_ * 2 * DD_];
__device__ __nv_bfloat16 g_cat_lo[(size_t)NN_ * 2 * DD_];
__device__ __nv_bfloat16 g_combn_hi[(size_t)NN_ * DD_];
__device__ __nv_bfloat16 g_combn_lo[(size_t)NN_ * DD_];
__device__ __nv_bfloat16 g_h_hi[(size_t)NN_ * FF_];
__device__ __nv_bfloat16 g_h_lo[(size_t)NN_ * FF_];
__device__ __nv_bfloat16 g_c2_hi[(size_t)NN_ * DD_];
__device__ __nv_bfloat16 g_c2_lo[(size_t)NN_ * DD_];

// fp32 intermediates
__device__ float g_comb[(size_t)NN_ * DD_];
__device__ float g_combn[(size_t)NN_ * DD_];      // fp32 kept for residual add
__device__ float g_r[(size_t)NN_ * DD_];
__device__ float g_dec[(size_t)NN_ * DD_];

// transposed + split weights (Wt[n][k] = W[k][n])
__device__ __nv_bfloat16 g_WdimT_hi[DD_ * DD_];
__device__ __nv_bfloat16 g_WdimT_lo[DD_ * DD_];
__device__ __nv_bfloat16 g_WfusT_hi[DD_ * 2 * DD_];
__device__ __nv_bfloat16 g_WfusT_lo[DD_ * 2 * DD_];
__device__ __nv_bfloat16 g_We1T_hi[(size_t)FF_ * DD_];
__device__ __nv_bfloat16 g_We1T_lo[(size_t)FF_ * DD_];
__device__ __nv_bfloat16 g_We2T_hi[(size_t)DD_ * FF_];
__device__ __nv_bfloat16 g_We2T_lo[(size_t)DD_ * FF_];
__device__ __nv_bfloat16 g_WdT_hi[DD_ * DD_];
__device__ __nv_bfloat16 g_WdT_lo[DD_ * DD_];

// BN
__device__ float g_part[2 * 128 * DD_];
__device__ float g_scale[DD_];
__device__ float g_shift[DD_];

// ---------------- helpers ----------------
__device__ __forceinline__ void split2(float x, float y,
                                       __nv_bfloat162& hi, __nv_bfloat162& lo) {
    hi = __floats2bfloat162_rn(x, y);
    float rx = x - __bfloat162float(hi.x);
    float ry = y - __bfloat162float(hi.y);
    lo = __floats2bfloat162_rn(rx, ry);
}

// ---------------- fp32 -> bf16 conversion (single, for distance GEMM) ----------------
__global__ void tobf16_kernel(const float* __restrict__ X, __nv_bfloat16* __restrict__ Y) {
    size_t i = ((size_t)blockIdx.x * 256 + threadIdx.x) * 4;
    float4 x = *reinterpret_cast<const float4*>(X + i);
    __nv_bfloat162 lo = __floats2bfloat162_rn(x.x, x.y);
    __nv_bfloat162 hi = __floats2bfloat162_rn(x.z, x.w);
    uint2 p;
    p.x = *reinterpret_cast<unsigned*>(&lo);
    p.y = *reinterpret_cast<unsigned*>(&hi);
    *reinterpret_cast<uint2*>(Y + i) = p;
}

// ---------------- src -> split bf16 into left half of concat ----------------
__global__ void pack_split_kernel(const float* __restrict__ src) {
    size_t i = ((size_t)blockIdx.x * 256 + threadIdx.x) * 4;   // over NN_*DD_
    size_t r = i >> 9;
    int c = (int)(i & 511);
    float4 x = *reinterpret_cast<const float4*>(src + i);
    __nv_bfloat162 h0, l0, h1, l1;
    split2(x.x, x.y, h0, l0);
    split2(x.z, x.w, h1, l1);
    uint2 ph, pl;
    ph.x = *reinterpret_cast<unsigned*>(&h0); ph.y = *reinterpret_cast<unsigned*>(&h1);
    pl.x = *reinterpret_cast<unsigned*>(&l0); pl.y = *reinterpret_cast<unsigned*>(&l1);
    *reinterpret_cast<uint2*>(g_cat_hi + r * 1024 + c) = ph;
    *reinterpret_cast<uint2*>(g_cat_lo + r * 1024 + c) = pl;
}

// ---------------- weight transpose + split: Thi/Tlo[n][k] = split(W[k][n]) ----------------
__global__ void tsplit_kernel(const float* __restrict__ W,
                              __nv_bfloat16* __restrict__ Thi,
                              __nv_bfloat16* __restrict__ Tlo, int K, int N) {
    __shared__ float tile[32][33];
    int n0 = blockIdx.x * 32, k0 = blockIdx.y * 32;
    int tx = threadIdx.x, ty = threadIdx.y;
    #pragma unroll
    for (int i = 0; i < 4; i++)
        tile[ty + i * 8][tx] = W[(size_t)(k0 + ty + i * 8) * N + n0 + tx];
    __syncthreads();
    #pragma unroll
    for (int i = 0; i < 4; i++) {
        int n = n0 + ty + i * 8;
        float v = tile[tx][ty + i * 8];
        __nv_bfloat16 h = __float2bfloat16(v);
        __nv_bfloat16 l = __float2bfloat16(v - __bfloat162float(h));
        Thi[(size_t)n * K + k0 + tx] = h;
        Tlo[(size_t)n * K + k0 + tx] = l;
    }
}

// ---------------- anchor squared norms ----------------
__global__ void anorm_kernel(const float* __restrict__ A) {
    int warp = threadIdx.x >> 5, lane = threadIdx.x & 31;
    int row = blockIdx.x * 8 + warp;
    const float* p = A + (size_t)row * DD_;
    float s = 0.f;
    for (int c = lane; c < DD_; c += 32) { float v = p[c]; s += v * v; }
    #pragma unroll
    for (int o = 16; o; o >>= 1) s += __shfl_xor_sync(0xffffffffu, s, o);
    if (lane == 0) g_anorm[row] = s;
}

// ---------------- bf16 tensor-core GEMM (NT), multi-pass hi/lo ----------------
// NPASS==1: C = Ahi * Bhi^T
// NPASS==3: C = Ahi*Bhi^T + Alo*Bhi^T + Ahi*Blo^T   (fp32-accurate split product)
// EPI: 0 = fp32 store, 1 = +bias fp32, 2 = +bias tanh -> split bf16,
//      3 = +bias +res fp32, 4 = +bias -> split bf16
#define LDS_BF 40

template <int NPASS, int EPI>
__global__ __launch_bounds__(256) void gemm_bf16_mp(
    const __nv_bfloat16* __restrict__ Ahi, const __nv_bfloat16* __restrict__ Alo,
    const __nv_bfloat16* __restrict__ Bhi, const __nv_bfloat16* __restrict__ Blo,
    const float* __restrict__ bias, const float* __restrict__ res,
    float* __restrict__ C, __nv_bfloat16* __restrict__ Chi,
    __nv_bfloat16* __restrict__ Clo,
    int K, int lda, int ldb, int ldc)
{
    __shared__ __nv_bfloat16 As[2][128 * LDS_BF];
    __shared__ __nv_bfloat16 Bs[2][128 * LDS_BF];
    const int tid = threadIdx.x;
    const int lane = tid & 31, w = tid >> 5;
    const int wr = w >> 2, wc = w & 3;
    const int rowBase = blockIdx.y * 128;
    const int colBase = blockIdx.x * 128;

    float acc[4][4][4];
    #pragma unroll
    for (int i = 0; i < 4; i++)
        #pragma unroll
        for (int j = 0; j < 4; j++)
            #pragma unroll
            for (int k = 0; k < 4; k++) acc[i][j][k] = 0.f;

    const int KT = K / 32;
    const int TT = NPASS * KT;

    #define ISSUE_TILE(t, buf)                                                     \
    {                                                                              \
        int p_ = (t) / KT;                                                         \
        int k0 = ((t) - p_ * KT) * 32;                                             \
        const __nv_bfloat16* Ab = (NPASS == 3 && p_ == 1) ? Alo : Ahi;             \
        const __nv_bfloat16* Bb = (NPASS == 3 && p_ == 2) ? Blo : Bhi;             \
        _Pragma("unroll")                                                          \
        for (int i = 0; i < 2; i++) {                                              \
            int v = tid + i * 256;                                                 \
            int r = v >> 2, c8 = (v & 3) * 8;                                      \
            unsigned sa = (unsigned)__cvta_generic_to_shared(                      \
                &As[buf][r * LDS_BF + c8]);                                        \
            const __nv_bfloat16* ga = Ab + (size_t)(rowBase + r) * lda + k0 + c8;  \
            asm volatile("cp.async.ca.shared.global [%0], [%1], 16;\n"             \
                         :: "r"(sa), "l"(ga));                                     \
            unsigned sb = (unsigned)__cvta_generic_to_shared(                      \
                &Bs[buf][r * LDS_BF + c8]);                                        \
            const __nv_bfloat16* gb = Bb + (size_t)(colBase + r) * ldb + k0 + c8;  \
            asm volatile("cp.async.ca.shared.global [%0], [%1], 16;\n"             \
                         :: "r"(sb), "l"(gb));                                     \
        }                                                                          \
        asm volatile("cp.async.commit_group;\n");                                  \
    }

    ISSUE_TILE(0, 0);

    for (int t = 0; t < TT; t++) {
        int buf = t & 1;
        if (t + 1 < TT) { ISSUE_TILE(t + 1, buf ^ 1); }
        else            { asm volatile("cp.async.commit_group;\n"); }
        asm volatile("cp.async.wait_group 1;\n");
        __syncthreads();

        #pragma unroll
        for (int ks = 0; ks < 2; ks++) {
            unsigned a[4][4], b[4][2];
            #pragma unroll
            for (int mt = 0; mt < 4; mt++) {
                int r = wr * 64 + mt * 16 + (lane & 15);
                int c = ks * 16 + (lane >> 4) * 8;
                unsigned addr = (unsigned)__cvta_generic_to_shared(
                    &As[buf][r * LDS_BF + c]);
                asm volatile(
                    "ldmatrix.sync.aligned.m8n8.x4.shared.b16 {%0,%1,%2,%3}, [%4];\n"
                    : "=r"(a[mt][0]), "=r"(a[mt][1]), "=r"(a[mt][2]), "=r"(a[mt][3])
                    : "r"(addr));
            }
            #pragma unroll
            for (int nt = 0; nt < 4; nt++) {
                int r = wc * 32 + nt * 8 + (lane & 7);
                int c = ks * 16 + ((lane >> 3) & 1) * 8;
                unsigned addr = (unsigned)__cvta_generic_to_shared(
                    &Bs[buf][r * LDS_BF + c]);
                asm volatile(
                    "ldmatrix.sync.aligned.m8n8.x2.shared.b16 {%0,%1}, [%2];\n"
                    : "=r"(b[nt][0]), "=r"(b[nt][1]) : "r"(addr));
            }
            #pragma unroll
            for (int mt = 0; mt < 4; mt++)
                #pragma unroll
                for (int nt = 0; nt < 4; nt++) {
                    float* c = acc[mt][nt];
                    asm volatile(
                        "mma.sync.aligned.m16n8k16.row.col.f32.bf16.bf16.f32 "
                        "{%0,%1,%2,%3}, {%4,%5,%6,%7}, {%8,%9}, {%0,%1,%2,%3};\n"
                        : "+f"(c[0]), "+f"(c[1]), "+f"(c[2]), "+f"(c[3])
                        : "r"(a[mt][0]), "r"(a[mt][1]), "r"(a[mt][2]), "r"(a[mt][3]),
                          "r"(b[nt][0]), "r"(b[nt][1]));
                }
        }
        __syncthreads();
    }
    #undef ISSUE_TILE

    // epilogue
    #pragma unroll
    for (int mt = 0; mt < 4; mt++) {
        int row0 = rowBase + wr * 64 + mt * 16 + (lane >> 2);
        #pragma unroll
        for (int nt = 0; nt < 4; nt++) {
            int col = colBase + wc * 32 + nt * 8 + (lane & 3) * 2;
            #pragma unroll
            for (int half = 0; half < 2; half++) {
                int row = row0 + half * 8;
                float vx = acc[mt][nt][half * 2 + 0];
                float vy = acc[mt][nt][half * 2 + 1];
                if (EPI >= 1) { vx += bias[col]; vy += bias[col + 1]; }
                if (EPI == 2) { vx = tanhf(vx); vy = tanhf(vy); }
                if (EPI == 3) {
                    const float2 rr = *reinterpret_cast<const float2*>(
                        res + (size_t)row * ldc + col);
                    vx += rr.x; vy += rr.y;
                }
                if (EPI == 2 || EPI == 4) {
                    __nv_bfloat162 h2, l2;
                    split2(vx, vy, h2, l2);
                    *reinterpret_cast<unsigned*>(Chi + (size_t)row * ldc + col) =
                        *reinterpret_cast<unsigned*>(&h2);
                    *reinterpret_cast<unsigned*>(Clo + (size_t)row * ldc + col) =
                        *reinterpret_cast<unsigned*>(&l2);
                } else {
                    *reinterpret_cast<float2*>(C + (size_t)row * ldc + col) =
                        make_float2(vx, vy);
                }
            }
        }
    }
}

// ---------------- coarse top-16 -> exact fp32 rescore -> top-5 + mean ----------------
// Phase 1: per-thread sorted top-16 via STATIC compare-swap bubble insert
//          (all indices compile-time constants -> lists live in registers).
// Phase 2: 16 extraction rounds, each = warp shfl lex-min (no barrier)
//          + cross-warp reduce (2 barriers/round). Exact lexicographic order.
__global__ __launch_bounds__(256) void topk16_kernel(
    const float* __restrict__ src, const float* __restrict__ anchors)
{
    int n = blockIdx.x;
    int tid = threadIdx.x;
    int lane = tid & 31, w = tid >> 5;
    const float* Srow = g_S + (size_t)n * MM_;

    float v[16]; int id[16];
    #pragma unroll
    for (int i = 0; i < 16; i++) { v[i] = 3.4e38f; id[i] = 0x7fffffff; }

    // each thread: 8 float4 = 32 elements of this row
    #pragma unroll
    for (int q = 0; q < 8; q++) {
        int m0 = q * 1024 + tid * 4;
        float4 s4 = *reinterpret_cast<const float4*>(Srow + m0);
        float4 a4 = *reinterpret_cast<const float4*>(g_anorm + m0);
        float dv[4] = { a4.x - 2.0f * s4.x, a4.y - 2.0f * s4.y,
                        a4.z - 2.0f * s4.z, a4.w - 2.0f * s4.w };
        #pragma unroll
        for (int u = 0; u < 4; u++) {
            float x = dv[u]; int xi = m0 + u;
            if (x < v[15] || (x == v[15] && xi < id[15])) {
                v[15] = x; id[15] = xi;
                #pragma unroll
                for (int k = 15; k > 0; k--) {
                    bool sw = (v[k] < v[k-1]) || (v[k] == v[k-1] && id[k] < id[k-1]);
                    float tv = sw ? v[k] : v[k-1];
                    float uv = sw ? v[k-1] : v[k];
                    int   ti = sw ? id[k] : id[k-1];
                    int   ui = sw ? id[k-1] : id[k];
                    v[k-1] = tv; v[k] = uv; id[k-1] = ti; id[k] = ui;
                }
            }
        }
    }

    // Phase 2: extract global top-16, one per round.
    __shared__ float wvv[8];
    __shared__ int   wvi[8];
    __shared__ int   sWin;
    __shared__ int   cand[16];

    #pragma unroll 1
    for (int round = 0; round < 16; round++) {
        // warp-level lex-min of each thread's head (v[0], id[0])
        float mv = v[0]; int mi = id[0];
        #pragma unroll
        for (int o = 16; o; o >>= 1) {
            float ov = __shfl_xor_sync(0xffffffffu, mv, o);
            int   oi = __shfl_xor_sync(0xffffffffu, mi, o);
            if (ov < mv || (ov == mv && oi < mi)) { mv = ov; mi = oi; }
        }
        if (lane == 0) { wvv[w] = mv; wvi[w] = mi; }
        __syncthreads();
        if (tid < 32) {
            float rv2 = (lane < 8) ? wvv[lane] : 3.4e38f;
            int   ri2 = (lane < 8) ? wvi[lane] : 0x7fffffff;
            #pragma unroll
            for (int o = 4; o; o >>= 1) {
                float ov = __shfl_xor_sync(0xffffffffu, rv2, o);
                int   oi = __shfl_xor_sync(0xffffffffu, ri2, o);
                if (ov < rv2 || (ov == rv2 && oi < ri2)) { rv2 = ov; ri2 = oi; }
            }
            if (lane == 0) { sWin = ri2; cand[round] = ri2; }
        }
        __syncthreads();
        // pop the winner from its owner's list (static shift-down)
        if (id[0] == sWin) {
            #pragma unroll
            for (int k = 0; k < 15; k++) { v[k] = v[k+1]; id[k] = id[k+1]; }
            v[15] = 3.4e38f; id[15] = 0x7fffffff;
        }
    }

    // exact fp32 rescore of 16 candidates (8 warps x 2 candidates)
    __shared__ float dex[16];
    const float* srow = src + (size_t)n * DD_;
    for (int c = w; c < 16; c += 8) {
        int m = cand[c];
        const float* a = anchors + (size_t)m * DD_;
        float s = 0.f;
        for (int i = lane; i < DD_; i += 32) s += srow[i] * a[i];
        #pragma unroll
        for (int o = 16; o; o >>= 1) s += __shfl_xor_sync(0xffffffffu, s, o);
        if (lane == 0) dex[c] = g_anorm[m] - 2.0f * s;
    }
    __syncthreads();

    __shared__ int win5[5];
    if (tid == 0) {
        bool used[16];
        #pragma unroll
        for (int i = 0; i < 16; i++) used[i] = false;
        for (int r2 = 0; r2 < 5; r2++) {
            float bv = 3.4e38f; int bi = 0x7fffffff; int bc = 0;
            for (int c = 0; c < 16; c++) {
                if (used[c]) continue;
                if (dex[c] < bv || (dex[c] == bv && cand[c] < bi)) {
                    bv = dex[c]; bi = cand[c]; bc = c;
                }
            }
            used[bc] = true; win5[r2] = bi;
        }
    }
    __syncthreads();

    // neigh mean -> split bf16
    for (int c = tid; c < DD_; c += 256) {
        float s = 0.f;
        #pragma unroll
        for (int k = 0; k < 5; k++) s += anchors[(size_t)win5[k] * DD_ + c];
        float m = s * 0.2f;
        __nv_bfloat16 h = __float2bfloat16(m);
        __nv_bfloat16 l = __float2bfloat16(m - __bfloat162float(h));
        g_neigh_hi[(size_t)n * DD_ + c] = h;
        g_neigh_lo[(size_t)n * DD_ + c] = l;
    }
}

// ---------------- BN: deterministic two-stage column stats ----------------
__global__ __launch_bounds__(256) void bn_stats_kernel(const float* __restrict__ X) {
    int b = blockIdx.x;
    int c0 = threadIdx.x, c1 = threadIdx.x + 256;
    float s0 = 0, q0 = 0, s1 = 0, q1 = 0;
    const float* p = X + (size_t)b * 128 * DD_;
    for (int r = 0; r < 128; r++) {
        float x0 = p[(size_t)r * DD_ + c0];
        float x1 = p[(size_t)r * DD_ + c1];
        s0 += x0; q0 += x0 * x0;
        s1 += x1; q1 += x1 * x1;
    }
    g_part[b * DD_ + c0] = s0;
    g_part[b * DD_ + c1] = s1;
    g_part[128 * DD_ + b * DD_ + c0] = q0;
    g_part[128 * DD_ + b * DD_ + c1] = q1;
}

__global__ void bn_finalize_kernel(const float* __restrict__ g,
                                   const float* __restrict__ bt) {
    int c = blockIdx.x * 256 + threadIdx.x;
    float s = 0, q = 0;
    for (int b = 0; b < 128; b++) {
        s += g_part[b * DD_ + c];
        q += g_part[128 * DD_ + b * DD_ + c];
    }
    float mu = s * (1.0f / NN_);
    float var = q * (1.0f / NN_) - mu * mu;
    float sc = g[c] * rsqrtf(var + 1e-5f);
    g_scale[c] = sc;
    g_shift[c] = bt[c] - mu * sc;
}

// BN apply; SPLIT: also emit hi/lo bf16 (same linear layout, ld=512)
template <bool TANH, bool SPLIT>
__global__ void bn_apply_kernel(const float* __restrict__ X, float* __restrict__ Y,
                                __nv_bfloat16* __restrict__ Yhi,
                                __nv_bfloat16* __restrict__ Ylo) {
    size_t i = ((size_t)blockIdx.x * 256 + threadIdx.x) * 4;
    int c = (int)(i & (DD_ - 1));
    float4 x  = *reinterpret_cast<const float4*>(X + i);
    float4 sc = *reinterpret_cast<const float4*>(g_scale + c);
    float4 sh = *reinterpret_cast<const float4*>(g_shift + c);
    float4 y;
    y.x = x.x * sc.x + sh.x; y.y = x.y * sc.y + sh.y;
    y.z = x.z * sc.z + sh.z; y.w = x.w * sc.w + sh.w;
    if (TANH) { y.x = tanhf(y.x); y.y = tanhf(y.y); y.z = tanhf(y.z); y.w = tanhf(y.w); }
    *reinterpret_cast<float4*>(Y + i) = y;
    if (SPLIT) {
        __nv_bfloat162 h0, l0, h1, l1;
        split2(y.x, y.y, h0, l0);
        split2(y.z, y.w, h1, l1);
        uint2 ph, pl;
        ph.x = *reinterpret_cast<unsigned*>(&h0); ph.y = *reinterpret_cast<unsigned*>(&h1);
        pl.x = *reinterpret_cast<unsigned*>(&l0); pl.y = *reinterpret_cast<unsigned*>(&l1);
        *reinterpret_cast<uint2*>(Yhi + i) = ph;
        *reinterpret_cast<uint2*>(Ylo + i) = pl;
    }
}

// ---------------- launch ----------------
static float* symAddr(const void* symbol) {
    void* p = nullptr;
    cudaGetSymbolAddress(&p, symbol);
    return (float*)p;
}

extern "C" void kernel_launch(void* const* d_in, const int* in_sizes, int n_in,
                              void* d_out, int out_size) {
    (void)in_sizes; (void)n_in; (void)out_size;
    const float* src    = (const float*)d_in[0];
    const float* anchor = (const float*)d_in[1];
    const float* W_dim  = (const float*)d_in[2];
    const float* b_dim  = (const float*)d_in[3];
    const float* W_fus  = (const float*)d_in[4];
    const float* b_fus  = (const float*)d_in[5];
    const float* W_e1   = (const float*)d_in[6];
    const float* b_e1   = (const float*)d_in[7];
    const float* W_e2   = (const float*)d_in[8];
    const float* b_e2   = (const float*)d_in[9];
    const float* g1     = (const float*)d_in[10];
    const float* bt1    = (const float*)d_in[11];
    const float* g2     = (const float*)d_in[12];
    const float* bt2    = (const float*)d_in[13];
    const float* W_d    = (const float*)d_in[14];
    const float* b_d    = (const float*)d_in[15];
    const float* g_d    = (const float*)d_in[16];
    const float* bt_d   = (const float*)d_in[17];
    float* out = (float*)d_out;

    float* pS      = symAddr(g_S);
    float* pComb   = symAddr(g_comb);
    float* pCombn  = symAddr(g_combn);
    float* pR      = symAddr(g_r);
    float* pDec    = symAddr(g_dec);
    __nv_bfloat16* pSrcBf   = (__nv_bfloat16*)symAddr(g_src_bf);
    __nv_bfloat16* pAnchBf  = (__nv_bfloat16*)symAddr(g_anch_bf);
    __nv_bfloat16* pNeighH  = (__nv_bfloat16*)symAddr(g_neigh_hi);
    __nv_bfloat16* pNeighL  = (__nv_bfloat16*)symAddr(g_neigh_lo);
    __nv_bfloat16* pCatH    = (__nv_bfloat16*)symAddr(g_cat_hi);
    __nv_bfloat16* pCatL    = (__nv_bfloat16*)symAddr(g_cat_lo);
    __nv_bfloat16* pCombnH  = (__nv_bfloat16*)symAddr(g_combn_hi);
    __nv_bfloat16* pCombnL  = (__nv_bfloat16*)symAddr(g_combn_lo);
    __nv_bfloat16* pHH      = (__nv_bfloat16*)symAddr(g_h_hi);
    __nv_bfloat16* pHL      = (__nv_bfloat16*)symAddr(g_h_lo);
    __nv_bfloat16* pC2H     = (__nv_bfloat16*)symAddr(g_c2_hi);
    __nv_bfloat16* pC2L     = (__nv_bfloat16*)symAddr(g_c2_lo);
    __nv_bfloat16* pWdimH   = (__nv_bfloat16*)symAddr(g_WdimT_hi);
    __nv_bfloat16* pWdimL   = (__nv_bfloat16*)symAddr(g_WdimT_lo);
    __nv_bfloat16* pWfusH   = (__nv_bfloat16*)symAddr(g_WfusT_hi);
    __nv_bfloat16* pWfusL   = (__nv_bfloat16*)symAddr(g_WfusT_lo);
    __nv_bfloat16* pWe1H    = (__nv_bfloat16*)symAddr(g_We1T_hi);
    __nv_bfloat16* pWe1L    = (__nv_bfloat16*)symAddr(g_We1T_lo);
    __nv_bfloat16* pWe2H    = (__nv_bfloat16*)symAddr(g_We2T_hi);
    __nv_bfloat16* pWe2L    = (__nv_bfloat16*)symAddr(g_We2T_lo);
    __nv_bfloat16* pWdH     = (__nv_bfloat16*)symAddr(g_WdT_hi);
    __nv_bfloat16* pWdL     = (__nv_bfloat16*)symAddr(g_WdT_lo);

    const int T = 256;

    // 0) bf16 copies for the coarse distance GEMM + weight transpose/split
    tobf16_kernel<<<(NN_ * DD_ / 4) / T, T>>>(src, pSrcBf);
    tobf16_kernel<<<(MM_ * DD_ / 4) / T, T>>>(anchor, pAnchBf);
    tsplit_kernel<<<dim3(DD_ / 32, DD_ / 32), dim3(32, 8)>>>(W_dim, pWdimH, pWdimL, DD_, DD_);
    tsplit_kernel<<<dim3(DD_ / 32, 2 * DD_ / 32), dim3(32, 8)>>>(W_fus, pWfusH, pWfusL, 2 * DD_, DD_);
    tsplit_kernel<<<dim3(FF_ / 32, DD_ / 32), dim3(32, 8)>>>(W_e1, pWe1H, pWe1L, DD_, FF_);
    tsplit_kernel<<<dim3(DD_ / 32, FF_ / 32), dim3(32, 8)>>>(W_e2, pWe2H, pWe2L, FF_, DD_);
    tsplit_kernel<<<dim3(DD_ / 32, DD_ / 32), dim3(32, 8)>>>(W_d, pWdH, pWdL, DD_, DD_);

    // 1) anchor norms (fp32)
    anorm_kernel<<<MM_ / 8, T>>>(anchor);

    // 2) coarse S = src_bf @ anchor_bf^T (single-pass bf16)
    gemm_bf16_mp<1, 0><<<dim3(MM_ / 128, NN_ / 128), T>>>(
        pSrcBf, nullptr, pAnchBf, nullptr, nullptr, nullptr,
        pS, nullptr, nullptr, DD_, DD_, DD_, MM_);

    // 3) top-16 -> exact rescore -> top-5 -> neigh (split bf16)
    topk16_kernel<<<NN_, T>>>(src, anchor);

    // 4) cat left = split(src); cat right = neigh @ W_dim + b_dim (split epilogue)
    pack_split_kernel<<<(NN_ * DD_ / 4) / T, T>>>(src);
    gemm_bf16_mp<3, 4><<<dim3(DD_ / 128, NN_ / 128), T>>>(
        pNeighH, pNeighL, pWdimH, pWdimL, b_dim, nullptr,
        nullptr, pCatH + DD_, pCatL + DD_, DD_, DD_, DD_, 2 * DD_);

    // 5) comb = cat @ W_fus + b_fus (K=1024) -> fp32
    gemm_bf16_mp<3, 1><<<dim3(DD_ / 128, NN_ / 128), T>>>(
        pCatH, pCatL, pWfusH, pWfusL, b_fus, nullptr,
        pComb, nullptr, nullptr, 2 * DD_, 2 * DD_, 2 * DD_, DD_);

    // 6) BN1 -> combn fp32 + split bf16
    bn_stats_kernel<<<128, T>>>(pComb);
    bn_finalize_kernel<<<2, T>>>(g1, bt1);
    bn_apply_kernel<false, true><<<(NN_ * DD_ / 4) / T, T>>>(pComb, pCombn, pCombnH, pCombnL);

    // 7) h = tanh(combn @ W_e1 + b_e1) -> split bf16 directly (no fp32 h)
    gemm_bf16_mp<3, 2><<<dim3(FF_ / 128, NN_ / 128), T>>>(
        pCombnH, pCombnL, pWe1H, pWe1L, b_e1, nullptr,
        nullptr, pHH, pHL, DD_, DD_, DD_, FF_);

    // 8) r = combn + (h @ W_e2 + b_e2) (K=2048) -> fp32
    gemm_bf16_mp<3, 3><<<dim3(DD_ / 128, NN_ / 128), T>>>(
        pHH, pHL, pWe2H, pWe2L, b_e2, pCombn,
        pR, nullptr, nullptr, FF_, FF_, FF_, DD_);

    // 9) BN2 -> comb2 split bf16
    bn_stats_kernel<<<128, T>>>(pR);
    bn_finalize_kernel<<<2, T>>>(g2, bt2);
    bn_apply_kernel<false, true><<<(NN_ * DD_ / 4) / T, T>>>(pR, pComb, pC2H, pC2L);

    // 10) dec = comb2 @ W_d + b_d -> fp32
    gemm_bf16_mp<3, 1><<<dim3(DD_ / 128, NN_ / 128), T>>>(
        pC2H, pC2L, pWdH, pWdL, b_d, nullptr,
        pDec, nullptr, nullptr, DD_, DD_, DD_, DD_);

    // 11) out = tanh(BN(dec))
    bn_stats_kernel<<<128, T>>>(pDec);
    bn_finalize_kernel<<<2, T>>>(g_d, bt_d);
    bn_apply_kernel<true, false><<<(NN_ * DD_ / 4) / T, T>>>(pDec, out, nullptr, nullptr);
}

// round 14
// speedup vs baseline: 2.6208x; 1.0080x over previous
#include <cuda_runtime.h>
#include <cuda_bf16.h>
#include <math.h>

// Problem constants
#define NN_ 16384
#define MM_ 8192
#define DD_ 512
#define FF_ 2048

// ---------------- static scratch (no runtime allocation allowed) ----------------
__device__ float g_anorm[MM_];
__device__ float g_S[(size_t)NN_ * MM_];          // 512 MB: coarse src @ anchor^T
__device__ __nv_bfloat16 g_anch_bf[(size_t)MM_ * DD_];

// split activations (hi/lo bf16)
__device__ __nv_bfloat16 g_neigh_hi[(size_t)NN_ * DD_];
__device__ __nv_bfloat16 g_neigh_lo[(size_t)NN_ * DD_];
__device__ __nv_bfloat16 g_cat_hi[(size_t)NN_ * 2 * DD_];   // left half = bf16(src)
__device__ __nv_bfloat16 g_cat_lo[(size_t)NN_ * 2 * DD_];
__device__ __nv_bfloat16 g_combn_hi[(size_t)NN_ * DD_];
__device__ __nv_bfloat16 g_combn_lo[(size_t)NN_ * DD_];
__device__ __nv_bfloat16 g_h_hi[(size_t)NN_ * FF_];
__device__ __nv_bfloat16 g_h_lo[(size_t)NN_ * FF_];
__device__ __nv_bfloat16 g_c2_hi[(size_t)NN_ * DD_];
__device__ __nv_bfloat16 g_c2_lo[(size_t)NN_ * DD_];

// fp32 intermediates
__device__ float g_comb[(size_t)NN_ * DD_];
__device__ float g_combn[(size_t)NN_ * DD_];      // fp32 kept for residual add
__device__ float g_r[(size_t)NN_ * DD_];
__device__ float g_dec[(size_t)NN_ * DD_];

// transposed + split weights (Wt[n][k] = W[k][n])
__device__ __nv_bfloat16 g_WdimT_hi[DD_ * DD_];
__device__ __nv_bfloat16 g_WdimT_lo[DD_ * DD_];
__device__ __nv_bfloat16 g_WfusT_hi[DD_ * 2 * DD_];
__device__ __nv_bfloat16 g_WfusT_lo[DD_ * 2 * DD_];
__device__ __nv_bfloat16 g_We1T_hi[(size_t)FF_ * DD_];
__device__ __nv_bfloat16 g_We1T_lo[(size_t)FF_ * DD_];
__device__ __nv_bfloat16 g_We2T_hi[(size_t)DD_ * FF_];
__device__ __nv_bfloat16 g_We2T_lo[(size_t)DD_ * FF_];
__device__ __nv_bfloat16 g_WdT_hi[DD_ * DD_];
__device__ __nv_bfloat16 g_WdT_lo[DD_ * DD_];

// BN
__device__ float g_part[2 * 128 * DD_];
__device__ float g_scale[DD_];
__device__ float g_shift[DD_];

// ---------------- helpers ----------------
__device__ __forceinline__ void split2(float x, float y,
                                       __nv_bfloat162& hi, __nv_bfloat162& lo) {
    hi = __floats2bfloat162_rn(x, y);
    float rx = x - __bfloat162float(hi.x);
    float ry = y - __bfloat162float(hi.y);
    lo = __floats2bfloat162_rn(rx, ry);
}

// ---------------- fp32 -> bf16 conversion (anchors, for distance GEMM) ----------------
__global__ void tobf16_kernel(const float* __restrict__ X, __nv_bfloat16* __restrict__ Y) {
    size_t i = ((size_t)blockIdx.x * 256 + threadIdx.x) * 4;
    float4 x = *reinterpret_cast<const float4*>(X + i);
    __nv_bfloat162 lo = __floats2bfloat162_rn(x.x, x.y);
    __nv_bfloat162 hi = __floats2bfloat162_rn(x.z, x.w);
    uint2 p;
    p.x = *reinterpret_cast<unsigned*>(&lo);
    p.y = *reinterpret_cast<unsigned*>(&hi);
    *reinterpret_cast<uint2*>(Y + i) = p;
}

// ---------------- src -> split bf16 into left half of concat ----------------
// NOTE: g_cat_hi left half == bf16_rn(src); reused as A operand of distance GEMM.
__global__ void pack_split_kernel(const float* __restrict__ src) {
    size_t i = ((size_t)blockIdx.x * 256 + threadIdx.x) * 4;   // over NN_*DD_
    size_t r = i >> 9;
    int c = (int)(i & 511);
    float4 x = *reinterpret_cast<const float4*>(src + i);
    __nv_bfloat162 h0, l0, h1, l1;
    split2(x.x, x.y, h0, l0);
    split2(x.z, x.w, h1, l1);
    uint2 ph, pl;
    ph.x = *reinterpret_cast<unsigned*>(&h0); ph.y = *reinterpret_cast<unsigned*>(&h1);
    pl.x = *reinterpret_cast<unsigned*>(&l0); pl.y = *reinterpret_cast<unsigned*>(&l1);
    *reinterpret_cast<uint2*>(g_cat_hi + r * 1024 + c) = ph;
    *reinterpret_cast<uint2*>(g_cat_lo + r * 1024 + c) = pl;
}

// ---------------- weight transpose + split: Thi/Tlo[n][k] = split(W[k][n]) ----------------
__global__ void tsplit_kernel(const float* __restrict__ W,
                              __nv_bfloat16* __restrict__ Thi,
                              __nv_bfloat16* __restrict__ Tlo, int K, int N) {
    __shared__ float tile[32][33];
    int n0 = blockIdx.x * 32, k0 = blockIdx.y * 32;
    int tx = threadIdx.x, ty = threadIdx.y;
    #pragma unroll
    for (int i = 0; i < 4; i++)
        tile[ty + i * 8][tx] = W[(size_t)(k0 + ty + i * 8) * N + n0 + tx];
    __syncthreads();
    #pragma unroll
    for (int i = 0; i < 4; i++) {
        int n = n0 + ty + i * 8;
        float v = tile[tx][ty + i * 8];
        __nv_bfloat16 h = __float2bfloat16(v);
        __nv_bfloat16 l = __float2bfloat16(v - __bfloat162float(h));
        Thi[(size_t)n * K + k0 + tx] = h;
        Tlo[(size_t)n * K + k0 + tx] = l;
    }
}

// ---------------- anchor squared norms ----------------
__global__ void anorm_kernel(const float* __restrict__ A) {
    int warp = threadIdx.x >> 5, lane = threadIdx.x & 31;
    int row = blockIdx.x * 8 + warp;
    const float* p = A + (size_t)row * DD_;
    float s = 0.f;
    for (int c = lane; c < DD_; c += 32) { float v = p[c]; s += v * v; }
    #pragma unroll
    for (int o = 16; o; o >>= 1) s += __shfl_xor_sync(0xffffffffu, s, o);
    if (lane == 0) g_anorm[row] = s;
}

// ---------------- bf16 tensor-core GEMM (NT), multi-pass hi/lo ----------------
// NPASS==1: C = Ahi * Bhi^T
// NPASS==3: C = Ahi*Bhi^T + Alo*Bhi^T + Ahi*Blo^T   (fp32-accurate split product)
// EPI: 0 = fp32 store, 1 = +bias fp32, 2 = +bias tanh -> split bf16,
//      3 = +bias +res fp32, 4 = +bias -> split bf16
#define LDS_BF 40

template <int NPASS, int EPI>
__global__ __launch_bounds__(256) void gemm_bf16_mp(
    const __nv_bfloat16* __restrict__ Ahi, const __nv_bfloat16* __restrict__ Alo,
    const __nv_bfloat16* __restrict__ Bhi, const __nv_bfloat16* __restrict__ Blo,
    const float* __restrict__ bias, const float* __restrict__ res,
    float* __restrict__ C, __nv_bfloat16* __restrict__ Chi,
    __nv_bfloat16* __restrict__ Clo,
    int K, int lda, int ldb, int ldc)
{
    __shared__ __nv_bfloat16 As[2][128 * LDS_BF];
    __shared__ __nv_bfloat16 Bs[2][128 * LDS_BF];
    const int tid = threadIdx.x;
    const int lane = tid & 31, w = tid >> 5;
    const int wr = w >> 2, wc = w & 3;
    const int rowBase = blockIdx.y * 128;
    const int colBase = blockIdx.x * 128;

    float acc[4][4][4];
    #pragma unroll
    for (int i = 0; i < 4; i++)
        #pragma unroll
        for (int j = 0; j < 4; j++)
            #pragma unroll
            for (int k = 0; k < 4; k++) acc[i][j][k] = 0.f;

    const int KT = K / 32;
    const int TT = NPASS * KT;

    #define ISSUE_TILE(t, buf)                                                     \
    {                                                                              \
        int p_ = (t) / KT;                                                         \
        int k0 = ((t) - p_ * KT) * 32;                                             \
        const __nv_bfloat16* Ab = (NPASS == 3 && p_ == 1) ? Alo : Ahi;             \
        const __nv_bfloat16* Bb = (NPASS == 3 && p_ == 2) ? Blo : Bhi;             \
        _Pragma("unroll")                                                          \
        for (int i = 0; i < 2; i++) {                                              \
            int v = tid + i * 256;                                                 \
            int r = v >> 2, c8 = (v & 3) * 8;                                      \
            unsigned sa = (unsigned)__cvta_generic_to_shared(                      \
                &As[buf][r * LDS_BF + c8]);                                        \
            const __nv_bfloat16* ga = Ab + (size_t)(rowBase + r) * lda + k0 + c8;  \
            asm volatile("cp.async.ca.shared.global [%0], [%1], 16;\n"             \
                         :: "r"(sa), "l"(ga));                                     \
            unsigned sb = (unsigned)__cvta_generic_to_shared(                      \
                &Bs[buf][r * LDS_BF + c8]);                                        \
            const __nv_bfloat16* gb = Bb + (size_t)(colBase + r) * ldb + k0 + c8;  \
            asm volatile("cp.async.ca.shared.global [%0], [%1], 16;\n"             \
                         :: "r"(sb), "l"(gb));                                     \
        }                                                                          \
        asm volatile("cp.async.commit_group;\n");                                  \
    }

    ISSUE_TILE(0, 0);

    for (int t = 0; t < TT; t++) {
        int buf = t & 1;
        if (t + 1 < TT) { ISSUE_TILE(t + 1, buf ^ 1); }
        else            { asm volatile("cp.async.commit_group;\n"); }
        asm volatile("cp.async.wait_group 1;\n");
        __syncthreads();

        #pragma unroll
        for (int ks = 0; ks < 2; ks++) {
            unsigned a[4][4], b[4][2];
            #pragma unroll
            for (int mt = 0; mt < 4; mt++) {
                int r = wr * 64 + mt * 16 + (lane & 15);
                int c = ks * 16 + (lane >> 4) * 8;
                unsigned addr = (unsigned)__cvta_generic_to_shared(
                    &As[buf][r * LDS_BF + c]);
                asm volatile(
                    "ldmatrix.sync.aligned.m8n8.x4.shared.b16 {%0,%1,%2,%3}, [%4];\n"
                    : "=r"(a[mt][0]), "=r"(a[mt][1]), "=r"(a[mt][2]), "=r"(a[mt][3])
                    : "r"(addr));
            }
            #pragma unroll
            for (int nt = 0; nt < 4; nt++) {
                int r = wc * 32 + nt * 8 + (lane & 7);
                int c = ks * 16 + ((lane >> 3) & 1) * 8;
                unsigned addr = (unsigned)__cvta_generic_to_shared(
                    &Bs[buf][r * LDS_BF + c]);
                asm volatile(
                    "ldmatrix.sync.aligned.m8n8.x2.shared.b16 {%0,%1}, [%2];\n"
                    : "=r"(b[nt][0]), "=r"(b[nt][1]) : "r"(addr));
            }
            #pragma unroll
            for (int mt = 0; mt < 4; mt++)
                #pragma unroll
                for (int nt = 0; nt < 4; nt++) {
                    float* c = acc[mt][nt];
                    asm volatile(
                        "mma.sync.aligned.m16n8k16.row.col.f32.bf16.bf16.f32 "
                        "{%0,%1,%2,%3}, {%4,%5,%6,%7}, {%8,%9}, {%0,%1,%2,%3};\n"
                        : "+f"(c[0]), "+f"(c[1]), "+f"(c[2]), "+f"(c[3])
                        : "r"(a[mt][0]), "r"(a[mt][1]), "r"(a[mt][2]), "r"(a[mt][3]),
                          "r"(b[nt][0]), "r"(b[nt][1]));
                }
        }
        __syncthreads();
    }
    #undef ISSUE_TILE

    // epilogue
    #pragma unroll
    for (int mt = 0; mt < 4; mt++) {
        int row0 = rowBase + wr * 64 + mt * 16 + (lane >> 2);
        #pragma unroll
        for (int nt = 0; nt < 4; nt++) {
            int col = colBase + wc * 32 + nt * 8 + (lane & 3) * 2;
            #pragma unroll
            for (int half = 0; half < 2; half++) {
                int row = row0 + half * 8;
                float vx = acc[mt][nt][half * 2 + 0];
                float vy = acc[mt][nt][half * 2 + 1];
                if (EPI >= 1) { vx += bias[col]; vy += bias[col + 1]; }
                if (EPI == 2) { vx = tanhf(vx); vy = tanhf(vy); }
                if (EPI == 3) {
                    const float2 rr = *reinterpret_cast<const float2*>(
                        res + (size_t)row * ldc + col);
                    vx += rr.x; vy += rr.y;
                }
                if (EPI == 2 || EPI == 4) {
                    __nv_bfloat162 h2, l2;
                    split2(vx, vy, h2, l2);
                    *reinterpret_cast<unsigned*>(Chi + (size_t)row * ldc + col) =
                        *reinterpret_cast<unsigned*>(&h2);
                    *reinterpret_cast<unsigned*>(Clo + (size_t)row * ldc + col) =
                        *reinterpret_cast<unsigned*>(&l2);
                } else {
                    *reinterpret_cast<float2*>(C + (size_t)row * ldc + col) =
                        make_float2(vx, vy);
                }
            }
        }
    }
}

// ---------------- coarse top-16 -> exact fp32 rescore -> top-5 + mean ----------------
// Phase 1: per-thread sorted top-16 via static compare-swap insert (registers).
// Phase 2a: per-warp sorted top-16 extraction, shfl-only (no block barriers).
// Phase 2b: warp 0 merges 8 sorted lists (16-step lane-parallel head-min).
// Output identical to block-wide tournament (lexicographic (value,index) order).
__global__ __launch_bounds__(256) void topk16_kernel(
    const float* __restrict__ src, const float* __restrict__ anchors)
{
    int n = blockIdx.x;
    int tid = threadIdx.x;
    int lane = tid & 31, w = tid >> 5;
    const float* Srow = g_S + (size_t)n * MM_;

    float v[16]; int id[16];
    #pragma unroll
    for (int i = 0; i < 16; i++) { v[i] = 3.4e38f; id[i] = 0x7fffffff; }

    // Phase 1: each thread scans 8 float4 = 32 elements
    #pragma unroll
    for (int q = 0; q < 8; q++) {
        int m0 = q * 1024 + tid * 4;
        float4 s4 = *reinterpret_cast<const float4*>(Srow + m0);
        float4 a4 = *reinterpret_cast<const float4*>(g_anorm + m0);
        float dv[4] = { a4.x - 2.0f * s4.x, a4.y - 2.0f * s4.y,
                        a4.z - 2.0f * s4.z, a4.w - 2.0f * s4.w };
        #pragma unroll
        for (int u = 0; u < 4; u++) {
            float x = dv[u]; int xi = m0 + u;
            if (x < v[15] || (x == v[15] && xi < id[15])) {
                v[15] = x; id[15] = xi;
                #pragma unroll
                for (int k = 15; k > 0; k--) {
                    bool sw = (v[k] < v[k-1]) || (v[k] == v[k-1] && id[k] < id[k-1]);
                    float tv = sw ? v[k] : v[k-1];
                    float uv = sw ? v[k-1] : v[k];
                    int   ti = sw ? id[k] : id[k-1];
                    int   ui = sw ? id[k-1] : id[k];
                    v[k-1] = tv; v[k] = uv; id[k-1] = ti; id[k] = ui;
                }
            }
        }
    }

    // Phase 2a: per-warp top-16 extraction (shfl only; all ids globally unique)
    __shared__ float s_lv[8 * 16];
    __shared__ int   s_li[8 * 16];
    #pragma unroll 1
    for (int r = 0; r < 16; r++) {
        float mv = v[0]; int mi = id[0];
        #pragma unroll
        for (int o = 16; o; o >>= 1) {
            float ov = __shfl_xor_sync(0xffffffffu, mv, o);
            int   oi = __shfl_xor_sync(0xffffffffu, mi, o);
            if (ov < mv || (ov == mv && oi < mi)) { mv = ov; mi = oi; }
        }
        if (lane == 0) { s_lv[w * 16 + r] = mv; s_li[w * 16 + r] = mi; }
        if (id[0] == mi) {
            #pragma unroll
            for (int k = 0; k < 15; k++) { v[k] = v[k+1]; id[k] = id[k+1]; }
            v[15] = 3.4e38f; id[15] = 0x7fffffff;
        }
    }
    __syncthreads();

    // Phase 2b: warp 0 merges the 8 sorted 16-lists into the global top-16
    __shared__ int cand[16];
    if (tid < 32) {
        int pos = 0;
        #pragma unroll 1
        for (int k = 0; k < 16; k++) {
            float hv = (lane < 8 && pos < 16) ? s_lv[lane * 16 + pos] : 3.4e38f;
            int   hi = (lane < 8 && pos < 16) ? s_li[lane * 16 + pos] : 0x7fffffff;
            float bv = hv; int bi = hi;
            #pragma unroll
            for (int o = 16; o; o >>= 1) {
                float ov = __shfl_xor_sync(0xffffffffu, bv, o);
                int   oi = __shfl_xor_sync(0xffffffffu, bi, o);
                if (ov < bv || (ov == bv && oi < bi)) { bv = ov; bi = oi; }
            }
            if (lane == 0) cand[k] = bi;
            if (hi == bi) pos++;   // unique ids -> exactly the owning lane advances
        }
    }
    __syncthreads();

    // exact fp32 rescore of 16 candidates (8 warps x 2 candidates)
    __shared__ float dex[16];
    const float* srow = src + (size_t)n * DD_;
    for (int c = w; c < 16; c += 8) {
        int m = cand[c];
        const float* a = anchors + (size_t)m * DD_;
        float s = 0.f;
        for (int i = lane; i < DD_; i += 32) s += srow[i] * a[i];
        #pragma unroll
        for (int o = 16; o; o >>= 1) s += __shfl_xor_sync(0xffffffffu, s, o);
        if (lane == 0) dex[c] = g_anorm[m] - 2.0f * s;
    }
    __syncthreads();

    __shared__ int win5[5];
    if (tid == 0) {
        bool used[16];
        #pragma unroll
        for (int i = 0; i < 16; i++) used[i] = false;
        for (int r2 = 0; r2 < 5; r2++) {
            float bv = 3.4e38f; int bi = 0x7fffffff; int bc = 0;
            for (int c = 0; c < 16; c++) {
                if (used[c]) continue;
                if (dex[c] < bv || (dex[c] == bv && cand[c] < bi)) {
                    bv = dex[c]; bi = cand[c]; bc = c;
                }
            }
            used[bc] = true; win5[r2] = bi;
        }
    }
    __syncthreads();

    // neigh mean -> split bf16
    for (int c = tid; c < DD_; c += 256) {
        float s = 0.f;
        #pragma unroll
        for (int k = 0; k < 5; k++) s += anchors[(size_t)win5[k] * DD_ + c];
        float m = s * 0.2f;
        __nv_bfloat16 h = __float2bfloat16(m);
        __nv_bfloat16 l = __float2bfloat16(m - __bfloat162float(h));
        g_neigh_hi[(size_t)n * DD_ + c] = h;
        g_neigh_lo[(size_t)n * DD_ + c] = l;
    }
}

// ---------------- BN: deterministic two-stage column stats ----------------
__global__ __launch_bounds__(256) void bn_stats_kernel(const float* __restrict__ X) {
    int b = blockIdx.x;
    int c0 = threadIdx.x, c1 = threadIdx.x + 256;
    float s0 = 0, q0 = 0, s1 = 0, q1 = 0;
    const float* p = X + (size_t)b * 128 * DD_;
    for (int r = 0; r < 128; r++) {
        float x0 = p[(size_t)r * DD_ + c0];
        float x1 = p[(size_t)r * DD_ + c1];
        s0 += x0; q0 += x0 * x0;
        s1 += x1; q1 += x1 * x1;
    }
    g_part[b * DD_ + c0] = s0;
    g_part[b * DD_ + c1] = s1;
    g_part[128 * DD_ + b * DD_ + c0] = q0;
    g_part[128 * DD_ + b * DD_ + c1] = q1;
}

__global__ void bn_finalize_kernel(const float* __restrict__ g,
                                   const float* __restrict__ bt) {
    int c = blockIdx.x * 256 + threadIdx.x;
    float s = 0, q = 0;
    for (int b = 0; b < 128; b++) {
        s += g_part[b * DD_ + c];
        q += g_part[128 * DD_ + b * DD_ + c];
    }
    float mu = s * (1.0f / NN_);
    float var = q * (1.0f / NN_) - mu * mu;
    float sc = g[c] * rsqrtf(var + 1e-5f);
    g_scale[c] = sc;
    g_shift[c] = bt[c] - mu * sc;
}

// BN apply; SPLIT: also emit hi/lo bf16 (same linear layout, ld=512)
template <bool TANH, bool SPLIT>
__global__ void bn_apply_kernel(const float* __restrict__ X, float* __restrict__ Y,
                                __nv_bfloat16* __restrict__ Yhi,
                                __nv_bfloat16* __restrict__ Ylo) {
    size_t i = ((size_t)blockIdx.x * 256 + threadIdx.x) * 4;
    int c = (int)(i & (DD_ - 1));
    float4 x  = *reinterpret_cast<const float4*>(X + i);
    float4 sc = *reinterpret_cast<const float4*>(g_scale + c);
    float4 sh = *reinterpret_cast<const float4*>(g_shift + c);
    float4 y;
    y.x = x.x * sc.x + sh.x; y.y = x.y * sc.y + sh.y;
    y.z = x.z * sc.z + sh.z; y.w = x.w * sc.w + sh.w;
    if (TANH) { y.x = tanhf(y.x); y.y = tanhf(y.y); y.z = tanhf(y.z); y.w = tanhf(y.w); }
    *reinterpret_cast<float4*>(Y + i) = y;
    if (SPLIT) {
        __nv_bfloat162 h0, l0, h1, l1;
        split2(y.x, y.y, h0, l0);
        split2(y.z, y.w, h1, l1);
        uint2 ph, pl;
        ph.x = *reinterpret_cast<unsigned*>(&h0); ph.y = *reinterpret_cast<unsigned*>(&h1);
        pl.x = *reinterpret_cast<unsigned*>(&l0); pl.y = *reinterpret_cast<unsigned*>(&l1);
        *reinterpret_cast<uint2*>(Yhi + i) = ph;
        *reinterpret_cast<uint2*>(Ylo + i) = pl;
    }
}

// ---------------- launch ----------------
static float* symAddr(const void* symbol) {
    void* p = nullptr;
    cudaGetSymbolAddress(&p, symbol);
    return (float*)p;
}

extern "C" void kernel_launch(void* const* d_in, const int* in_sizes, int n_in,
                              void* d_out, int out_size) {
    (void)in_sizes; (void)n_in; (void)out_size;
    const float* src    = (const float*)d_in[0];
    const float* anchor = (const float*)d_in[1];
    const float* W_dim  = (const float*)d_in[2];
    const float* b_dim  = (const float*)d_in[3];
    const float* W_fus  = (const float*)d_in[4];
    const float* b_fus  = (const float*)d_in[5];
    const float* W_e1   = (const float*)d_in[6];
    const float* b_e1   = (const float*)d_in[7];
    const float* W_e2   = (const float*)d_in[8];
    const float* b_e2   = (const float*)d_in[9];
    const float* g1     = (const float*)d_in[10];
    const float* bt1    = (const float*)d_in[11];
    const float* g2     = (const float*)d_in[12];
    const float* bt2    = (const float*)d_in[13];
    const float* W_d    = (const float*)d_in[14];
    const float* b_d    = (const float*)d_in[15];
    const float* g_d    = (const float*)d_in[16];
    const float* bt_d   = (const float*)d_in[17];
    float* out = (float*)d_out;

    float* pS      = symAddr(g_S);
    float* pComb   = symAddr(g_comb);
    float* pCombn  = symAddr(g_combn);
    float* pR      = symAddr(g_r);
    float* pDec    = symAddr(g_dec);
    __nv_bfloat16* pAnchBf  = (__nv_bfloat16*)symAddr(g_anch_bf);
    __nv_bfloat16* pNeighH  = (__nv_bfloat16*)symAddr(g_neigh_hi);
    __nv_bfloat16* pNeighL  = (__nv_bfloat16*)symAddr(g_neigh_lo);
    __nv_bfloat16* pCatH    = (__nv_bfloat16*)symAddr(g_cat_hi);
    __nv_bfloat16* pCatL    = (__nv_bfloat16*)symAddr(g_cat_lo);
    __nv_bfloat16* pCombnH  = (__nv_bfloat16*)symAddr(g_combn_hi);
    __nv_bfloat16* pCombnL  = (__nv_bfloat16*)symAddr(g_combn_lo);
    __nv_bfloat16* pHH      = (__nv_bfloat16*)symAddr(g_h_hi);
    __nv_bfloat16* pHL      = (__nv_bfloat16*)symAddr(g_h_lo);
    __nv_bfloat16* pC2H     = (__nv_bfloat16*)symAddr(g_c2_hi);
    __nv_bfloat16* pC2L     = (__nv_bfloat16*)symAddr(g_c2_lo);
    __nv_bfloat16* pWdimH   = (__nv_bfloat16*)symAddr(g_WdimT_hi);
    __nv_bfloat16* pWdimL   = (__nv_bfloat16*)symAddr(g_WdimT_lo);
    __nv_bfloat16* pWfusH   = (__nv_bfloat16*)symAddr(g_WfusT_hi);
    __nv_bfloat16* pWfusL   = (__nv_bfloat16*)symAddr(g_WfusT_lo);
    __nv_bfloat16* pWe1H    = (__nv_bfloat16*)symAddr(g_We1T_hi);
    __nv_bfloat16* pWe1L    = (__nv_bfloat16*)symAddr(g_We1T_lo);
    __nv_bfloat16* pWe2H    = (__nv_bfloat16*)symAddr(g_We2T_hi);
    __nv_bfloat16* pWe2L    = (__nv_bfloat16*)symAddr(g_We2T_lo);
    __nv_bfloat16* pWdH     = (__nv_bfloat16*)symAddr(g_WdT_hi);
    __nv_bfloat16* pWdL     = (__nv_bfloat16*)symAddr(g_WdT_lo);

    const int T = 256;

    // Launch order arranged so ncu (-s 5 -c 1) captures topk16 (launch index 5).
    // 0) anchors -> bf16
    tobf16_kernel<<<(MM_ * DD_ / 4) / T, T>>>(anchor, pAnchBf);
    // 1) src -> split bf16 into cat (cat_hi left half == bf16(src), reused below)
    pack_split_kernel<<<(NN_ * DD_ / 4) / T, T>>>(src);
    // 2) anchor norms (fp32)
    anorm_kernel<<<MM_ / 8, T>>>(anchor);
    // 3) coarse S = bf16(src) @ anchor_bf^T  (A = cat_hi left half, lda = 1024)
    gemm_bf16_mp<1, 0><<<dim3(MM_ / 128, NN_ / 128), T>>>(
        pCatH, nullptr, pAnchBf, nullptr, nullptr, nullptr,
        pS, nullptr, nullptr, DD_, 2 * DD_, DD_, MM_);
    // 4) one weight split (independent filler so topk is launch #5)
    tsplit_kernel<<<dim3(DD_ / 32, DD_ / 32), dim3(32, 8)>>>(W_dim, pWdimH, pWdimL, DD_, DD_);
    // 5) top-16 -> exact rescore -> top-5 -> neigh (split bf16)   [ncu captures this]
    topk16_kernel<<<NN_, T>>>(src, anchor);

    // remaining weight splits
    tsplit_kernel<<<dim3(DD_ / 32, 2 * DD_ / 32), dim3(32, 8)>>>(W_fus, pWfusH, pWfusL, 2 * DD_, DD_);
    tsplit_kernel<<<dim3(FF_ / 32, DD_ / 32), dim3(32, 8)>>>(W_e1, pWe1H, pWe1L, DD_, FF_);
    tsplit_kernel<<<dim3(DD_ / 32, FF_ / 32), dim3(32, 8)>>>(W_e2, pWe2H, pWe2L, FF_, DD_);
    tsplit_kernel<<<dim3(DD_ / 32, DD_ / 32), dim3(32, 8)>>>(W_d, pWdH, pWdL, DD_, DD_);

    // cat right = neigh @ W_dim + b_dim (split epilogue)
    gemm_bf16_mp<3, 4><<<dim3(DD_ / 128, NN_ / 128), T>>>(
        pNeighH, pNeighL, pWdimH, pWdimL, b_dim, nullptr,
        nullptr, pCatH + DD_, pCatL + DD_, DD_, DD_, DD_, 2 * DD_);

    // comb = cat @ W_fus + b_fus (K=1024) -> fp32
    gemm_bf16_mp<3, 1><<<dim3(DD_ / 128, NN_ / 128), T>>>(
        pCatH, pCatL, pWfusH, pWfusL, b_fus, nullptr,
        pComb, nullptr, nullptr, 2 * DD_, 2 * DD_, 2 * DD_, DD_);

    // BN1 -> combn fp32 + split bf16
    bn_stats_kernel<<<128, T>>>(pComb);
    bn_finalize_kernel<<<2, T>>>(g1, bt1);
    bn_apply_kernel<false, true><<<(NN_ * DD_ / 4) / T, T>>>(pComb, pCombn, pCombnH, pCombnL);

    // h = tanh(combn @ W_e1 + b_e1) -> split bf16 directly (no fp32 h)
    gemm_bf16_mp<3, 2><<<dim3(FF_ / 128, NN_ / 128), T>>>(
        pCombnH, pCombnL, pWe1H, pWe1L, b_e1, nullptr,
        nullptr, pHH, pHL, DD_, DD_, DD_, FF_);

    // r = combn + (h @ W_e2 + b_e2) (K=2048) -> fp32
    gemm_bf16_mp<3, 3><<<dim3(DD_ / 128, NN_ / 128), T>>>(
        pHH, pHL, pWe2H, pWe2L, b_e2, pCombn,
        pR, nullptr, nullptr, FF_, FF_, FF_, DD_);

    // BN2 -> comb2 split bf16
    bn_stats_kernel<<<128, T>>>(pR);
    bn_finalize_kernel<<<2, T>>>(g2, bt2);
    bn_apply_kernel<false, true><<<(NN_ * DD_ / 4) / T, T>>>(pR, pComb, pC2H, pC2L);

    // dec = comb2 @ W_d + b_d -> fp32
    gemm_bf16_mp<3, 1><<<dim3(DD_ / 128, NN_ / 128), T>>>(
        pC2H, pC2L, pWdH, pWdL, b_d, nullptr,
        pDec, nullptr, nullptr, DD_, DD_, DD_, DD_);

    // out = tanh(BN(dec))
    bn_stats_kernel<<<128, T>>>(pDec);
    bn_finalize_kernel<<<2, T>>>(g_d, bt_d);
    bn_apply_kernel<true, false><<<(NN_ * DD_ / 4) / T, T>>>(pDec, out, nullptr, nullptr);
}

// round 16
// speedup vs baseline: 2.7325x; 1.0426x over previous
#include <cuda_runtime.h>
#include <cuda_bf16.h>
#include <math.h>

// Problem constants
#define NN_ 16384
#define MM_ 8192
#define DD_ 512
#define FF_ 2048

// ---------------- static scratch (no runtime allocation allowed) ----------------
__device__ float g_anorm[MM_];
__device__ __nv_bfloat16 g_S_bf[(size_t)NN_ * MM_];   // 256 MB: coarse scores (bf16)
__device__ __nv_bfloat16 g_anch_bf[(size_t)MM_ * DD_];

// split activations (hi/lo bf16)
__device__ __nv_bfloat16 g_neigh_hi[(size_t)NN_ * DD_];
__device__ __nv_bfloat16 g_neigh_lo[(size_t)NN_ * DD_];
__device__ __nv_bfloat16 g_cat_hi[(size_t)NN_ * 2 * DD_];   // left half = bf16(src)
__device__ __nv_bfloat16 g_cat_lo[(size_t)NN_ * 2 * DD_];
__device__ __nv_bfloat16 g_combn_hi[(size_t)NN_ * DD_];
__device__ __nv_bfloat16 g_combn_lo[(size_t)NN_ * DD_];
__device__ __nv_bfloat16 g_h_hi[(size_t)NN_ * FF_];
__device__ __nv_bfloat16 g_h_lo[(size_t)NN_ * FF_];
__device__ __nv_bfloat16 g_c2_hi[(size_t)NN_ * DD_];
__device__ __nv_bfloat16 g_c2_lo[(size_t)NN_ * DD_];

// fp32 intermediates
__device__ float g_comb[(size_t)NN_ * DD_];
__device__ float g_combn[(size_t)NN_ * DD_];      // fp32 kept for residual add
__device__ float g_r[(size_t)NN_ * DD_];
__device__ float g_dec[(size_t)NN_ * DD_];

// transposed + split weights (Wt[n][k] = W[k][n])
__device__ __nv_bfloat16 g_WdimT_hi[DD_ * DD_];
__device__ __nv_bfloat16 g_WdimT_lo[DD_ * DD_];
__device__ __nv_bfloat16 g_WfusT_hi[DD_ * 2 * DD_];
__device__ __nv_bfloat16 g_WfusT_lo[DD_ * 2 * DD_];
__device__ __nv_bfloat16 g_We1T_hi[(size_t)FF_ * DD_];
__device__ __nv_bfloat16 g_We1T_lo[(size_t)FF_ * DD_];
__device__ __nv_bfloat16 g_We2T_hi[(size_t)DD_ * FF_];
__device__ __nv_bfloat16 g_We2T_lo[(size_t)DD_ * FF_];
__device__ __nv_bfloat16 g_WdT_hi[DD_ * DD_];
__device__ __nv_bfloat16 g_WdT_lo[DD_ * DD_];

// BN
__device__ float g_part[2 * 128 * DD_];
__device__ float g_scale[DD_];
__device__ float g_shift[DD_];

// ---------------- helpers ----------------
__device__ __forceinline__ void split2(float x, float y,
                                       __nv_bfloat162& hi, __nv_bfloat162& lo) {
    hi = __floats2bfloat162_rn(x, y);
    float rx = x - __bfloat162float(hi.x);
    float ry = y - __bfloat162float(hi.y);
    lo = __floats2bfloat162_rn(rx, ry);
}

// ---------------- fp32 -> bf16 conversion (anchors, for distance GEMM) ----------------
__global__ void tobf16_kernel(const float* __restrict__ X, __nv_bfloat16* __restrict__ Y) {
    size_t i = ((size_t)blockIdx.x * 256 + threadIdx.x) * 4;
    float4 x = *reinterpret_cast<const float4*>(X + i);
    __nv_bfloat162 lo = __floats2bfloat162_rn(x.x, x.y);
    __nv_bfloat162 hi = __floats2bfloat162_rn(x.z, x.w);
    uint2 p;
    p.x = *reinterpret_cast<unsigned*>(&lo);
    p.y = *reinterpret_cast<unsigned*>(&hi);
    *reinterpret_cast<uint2*>(Y + i) = p;
}

// ---------------- src -> split bf16 into left half of concat ----------------
// NOTE: g_cat_hi left half == bf16_rn(src); reused as A operand of distance GEMM.
__global__ void pack_split_kernel(const float* __restrict__ src) {
    size_t i = ((size_t)blockIdx.x * 256 + threadIdx.x) * 4;   // over NN_*DD_
    size_t r = i >> 9;
    int c = (int)(i & 511);
    float4 x = *reinterpret_cast<const float4*>(src + i);
    __nv_bfloat162 h0, l0, h1, l1;
    split2(x.x, x.y, h0, l0);
    split2(x.z, x.w, h1, l1);
    uint2 ph, pl;
    ph.x = *reinterpret_cast<unsigned*>(&h0); ph.y = *reinterpret_cast<unsigned*>(&h1);
    pl.x = *reinterpret_cast<unsigned*>(&l0); pl.y = *reinterpret_cast<unsigned*>(&l1);
    *reinterpret_cast<uint2*>(g_cat_hi + r * 1024 + c) = ph;
    *reinterpret_cast<uint2*>(g_cat_lo + r * 1024 + c) = pl;
}

// ---------------- weight transpose + split: Thi/Tlo[n][k] = split(W[k][n]) ----------------
__global__ void tsplit_kernel(const float* __restrict__ W,
                              __nv_bfloat16* __restrict__ Thi,
                              __nv_bfloat16* __restrict__ Tlo, int K, int N) {
    __shared__ float tile[32][33];
    int n0 = blockIdx.x * 32, k0 = blockIdx.y * 32;
    int tx = threadIdx.x, ty = threadIdx.y;
    #pragma unroll
    for (int i = 0; i < 4; i++)
        tile[ty + i * 8][tx] = W[(size_t)(k0 + ty + i * 8) * N + n0 + tx];
    __syncthreads();
    #pragma unroll
    for (int i = 0; i < 4; i++) {
        int n = n0 + ty + i * 8;
        float v = tile[tx][ty + i * 8];
        __nv_bfloat16 h = __float2bfloat16(v);
        __nv_bfloat16 l = __float2bfloat16(v - __bfloat162float(h));
        Thi[(size_t)n * K + k0 + tx] = h;
        Tlo[(size_t)n * K + k0 + tx] = l;
    }
}

// ---------------- anchor squared norms ----------------
__global__ void anorm_kernel(const float* __restrict__ A) {
    int warp = threadIdx.x >> 5, lane = threadIdx.x & 31;
    int row = blockIdx.x * 8 + warp;
    const float* p = A + (size_t)row * DD_;
    float s = 0.f;
    for (int c = lane; c < DD_; c += 32) { float v = p[c]; s += v * v; }
    #pragma unroll
    for (int o = 16; o; o >>= 1) s += __shfl_xor_sync(0xffffffffu, s, o);
    if (lane == 0) g_anorm[row] = s;
}

// ---------------- bf16 tensor-core GEMM (NT), multi-pass hi/lo, 3-stage pipeline ----
// NPASS==1: C = Ahi * Bhi^T
// NPASS==3: C = Ahi*Bhi^T + Alo*Bhi^T + Ahi*Blo^T   (fp32-accurate split product)
// EPI: 0 = fp32 store, 1 = +bias fp32, 2 = +bias tanh -> split bf16,
//      3 = +bias +res fp32, 4 = +bias -> split bf16, 5 = bf16 store (no bias)
#define LDS_BF 40
#define GEMM_SMEM (3 * 128 * LDS_BF * 2 * 2)   // 3 stages x (A+B) x 128 x LDS_BF bf16

template <int NPASS, int EPI>
__global__ __launch_bounds__(256) void gemm_bf16_mp(
    const __nv_bfloat16* __restrict__ Ahi, const __nv_bfloat16* __restrict__ Alo,
    const __nv_bfloat16* __restrict__ Bhi, const __nv_bfloat16* __restrict__ Blo,
    const float* __restrict__ bias, const float* __restrict__ res,
    float* __restrict__ C, __nv_bfloat16* __restrict__ Chi,
    __nv_bfloat16* __restrict__ Clo,
    int K, int lda, int ldb, int ldc)
{
    extern __shared__ __nv_bfloat16 smem_bf[];
    __nv_bfloat16* As = smem_bf;                       // [3][128*LDS_BF]
    __nv_bfloat16* Bs = smem_bf + 3 * 128 * LDS_BF;    // [3][128*LDS_BF]
    const int tid = threadIdx.x;
    const int lane = tid & 31, w = tid >> 5;
    const int wr = w >> 2, wc = w & 3;
    const int rowBase = blockIdx.y * 128;
    const int colBase = blockIdx.x * 128;

    float acc[4][4][4];
    #pragma unroll
    for (int i = 0; i < 4; i++)
        #pragma unroll
        for (int j = 0; j < 4; j++)
            #pragma unroll
            for (int k = 0; k < 4; k++) acc[i][j][k] = 0.f;

    const int KT = K / 32;
    const int TT = NPASS * KT;

    #define ISSUE_TILE(t, buf)                                                     \
    {                                                                              \
        int p_ = (t) / KT;                                                         \
        int k0 = ((t) - p_ * KT) * 32;                                             \
        const __nv_bfloat16* Ab = (NPASS == 3 && p_ == 1) ? Alo : Ahi;             \
        const __nv_bfloat16* Bb = (NPASS == 3 && p_ == 2) ? Blo : Bhi;             \
        _Pragma("unroll")                                                          \
        for (int i = 0; i < 2; i++) {                                              \
            int v = tid + i * 256;                                                 \
            int r = v >> 2, c8 = (v & 3) * 8;                                      \
            unsigned sa = (unsigned)__cvta_generic_to_shared(                      \
                As + (buf) * 128 * LDS_BF + r * LDS_BF + c8);                      \
            const __nv_bfloat16* ga = Ab + (size_t)(rowBase + r) * lda + k0 + c8;  \
            asm volatile("cp.async.ca.shared.global [%0], [%1], 16;\n"             \
                         :: "r"(sa), "l"(ga));                                     \
            unsigned sb = (unsigned)__cvta_generic_to_shared(                      \
                Bs + (buf) * 128 * LDS_BF + r * LDS_BF + c8);                      \
            const __nv_bfloat16* gb = Bb + (size_t)(colBase + r) * ldb + k0 + c8;  \
            asm volatile("cp.async.ca.shared.global [%0], [%1], 16;\n"             \
                         :: "r"(sb), "l"(gb));                                     \
        }                                                                          \
        asm volatile("cp.async.commit_group;\n");                                  \
    }

    ISSUE_TILE(0, 0);
    ISSUE_TILE(1, 1);

    for (int t = 0; t < TT; t++) {
        int buf = t % 3;
        if (t + 2 < TT) { ISSUE_TILE(t + 2, (t + 2) % 3); }
        else            { asm volatile("cp.async.commit_group;\n"); }
        asm volatile("cp.async.wait_group 2;\n");
        __syncthreads();

        #pragma unroll
        for (int ks = 0; ks < 2; ks++) {
            unsigned a[4][4], b[4][2];
            #pragma unroll
            for (int mt = 0; mt < 4; mt++) {
                int r = wr * 64 + mt * 16 + (lane & 15);
                int c = ks * 16 + (lane >> 4) * 8;
                unsigned addr = (unsigned)__cvta_generic_to_shared(
                    As + buf * 128 * LDS_BF + r * LDS_BF + c);
                asm volatile(
                    "ldmatrix.sync.aligned.m8n8.x4.shared.b16 {%0,%1,%2,%3}, [%4];\n"
                    : "=r"(a[mt][0]), "=r"(a[mt][1]), "=r"(a[mt][2]), "=r"(a[mt][3])
                    : "r"(addr));
            }
            #pragma unroll
            for (int nt = 0; nt < 4; nt++) {
                int r = wc * 32 + nt * 8 + (lane & 7);
                int c = ks * 16 + ((lane >> 3) & 1) * 8;
                unsigned addr = (unsigned)__cvta_generic_to_shared(
                    Bs + buf * 128 * LDS_BF + r * LDS_BF + c);
                asm volatile(
                    "ldmatrix.sync.aligned.m8n8.x2.shared.b16 {%0,%1}, [%2];\n"
                    : "=r"(b[nt][0]), "=r"(b[nt][1]) : "r"(addr));
            }
            #pragma unroll
            for (int mt = 0; mt < 4; mt++)
                #pragma unroll
                for (int nt = 0; nt < 4; nt++) {
                    float* c = acc[mt][nt];
                    asm volatile(
                        "mma.sync.aligned.m16n8k16.row.col.f32.bf16.bf16.f32 "
                        "{%0,%1,%2,%3}, {%4,%5,%6,%7}, {%8,%9}, {%0,%1,%2,%3};\n"
                        : "+f"(c[0]), "+f"(c[1]), "+f"(c[2]), "+f"(c[3])
                        : "r"(a[mt][0]), "r"(a[mt][1]), "r"(a[mt][2]), "r"(a[mt][3]),
                          "r"(b[nt][0]), "r"(b[nt][1]));
                }
        }
        __syncthreads();
    }
    #undef ISSUE_TILE

    // epilogue
    #pragma unroll
    for (int mt = 0; mt < 4; mt++) {
        int row0 = rowBase + wr * 64 + mt * 16 + (lane >> 2);
        #pragma unroll
        for (int nt = 0; nt < 4; nt++) {
            int col = colBase + wc * 32 + nt * 8 + (lane & 3) * 2;
            #pragma unroll
            for (int half = 0; half < 2; half++) {
                int row = row0 + half * 8;
                float vx = acc[mt][nt][half * 2 + 0];
                float vy = acc[mt][nt][half * 2 + 1];
                if (EPI >= 1 && EPI != 5) { vx += bias[col]; vy += bias[col + 1]; }
                if (EPI == 2) { vx = tanhf(vx); vy = tanhf(vy); }
                if (EPI == 3) {
                    const float2 rr = *reinterpret_cast<const float2*>(
                        res + (size_t)row * ldc + col);
                    vx += rr.x; vy += rr.y;
                }
                if (EPI == 5) {
                    __nv_bfloat162 h2 = __floats2bfloat162_rn(vx, vy);
                    *reinterpret_cast<unsigned*>(Chi + (size_t)row * ldc + col) =
                        *reinterpret_cast<unsigned*>(&h2);
                } else if (EPI == 2 || EPI == 4) {
                    __nv_bfloat162 h2, l2;
                    split2(vx, vy, h2, l2);
                    *reinterpret_cast<unsigned*>(Chi + (size_t)row * ldc + col) =
                        *reinterpret_cast<unsigned*>(&h2);
                    *reinterpret_cast<unsigned*>(Clo + (size_t)row * ldc + col) =
                        *reinterpret_cast<unsigned*>(&l2);
                } else {
                    *reinterpret_cast<float2*>(C + (size_t)row * ldc + col) =
                        make_float2(vx, vy);
                }
            }
        }
    }
}

// ---------------- coarse top-16 -> exact fp32 rescore -> top-5 + mean ----------------
// S is bf16 (coarse): quantization error (<=0.2 in d^2) stays far inside the
// rank5->rank16 margin (~18), and final top-5 comes from the exact fp32 rescore.
__global__ __launch_bounds__(256) void topk16_kernel(
    const float* __restrict__ src, const float* __restrict__ anchors)
{
    int n = blockIdx.x;
    int tid = threadIdx.x;
    int lane = tid & 31, w = tid >> 5;
    const __nv_bfloat16* Srow = g_S_bf + (size_t)n * MM_;

    float v[16]; int id[16];
    #pragma unroll
    for (int i = 0; i < 16; i++) { v[i] = 3.4e38f; id[i] = 0x7fffffff; }

    // Phase 1: each thread scans 4 x uint4 = 32 bf16 elements
    #pragma unroll
    for (int q = 0; q < 4; q++) {
        int m0 = q * 2048 + tid * 8;
        uint4 sp = *reinterpret_cast<const uint4*>(Srow + m0);
        float4 a0 = *reinterpret_cast<const float4*>(g_anorm + m0);
        float4 a1 = *reinterpret_cast<const float4*>(g_anorm + m0 + 4);
        float2 s01 = __bfloat1622float2(*reinterpret_cast<__nv_bfloat162*>(&sp.x));
        float2 s23 = __bfloat1622float2(*reinterpret_cast<__nv_bfloat162*>(&sp.y));
        float2 s45 = __bfloat1622float2(*reinterpret_cast<__nv_bfloat162*>(&sp.z));
        float2 s67 = __bfloat1622float2(*reinterpret_cast<__nv_bfloat162*>(&sp.w));
        float dv[8] = { a0.x - 2.0f * s01.x, a0.y - 2.0f * s01.y,
                        a0.z - 2.0f * s23.x, a0.w - 2.0f * s23.y,
                        a1.x - 2.0f * s45.x, a1.y - 2.0f * s45.y,
                        a1.z - 2.0f * s67.x, a1.w - 2.0f * s67.y };
        #pragma unroll
        for (int u = 0; u < 8; u++) {
            float x = dv[u]; int xi = m0 + u;
            if (x < v[15] || (x == v[15] && xi < id[15])) {
                v[15] = x; id[15] = xi;
                #pragma unroll
                for (int k = 15; k > 0; k--) {
                    bool sw = (v[k] < v[k-1]) || (v[k] == v[k-1] && id[k] < id[k-1]);
                    float tv = sw ? v[k] : v[k-1];
                    float uv = sw ? v[k-1] : v[k];
                    int   ti = sw ? id[k] : id[k-1];
                    int   ui = sw ? id[k-1] : id[k];
                    v[k-1] = tv; v[k] = uv; id[k-1] = ti; id[k] = ui;
                }
            }
        }
    }

    // Phase 2a: per-warp top-16 extraction (shfl only; all ids globally unique)
    __shared__ float s_lv[8 * 16];
    __shared__ int   s_li[8 * 16];
    #pragma unroll 1
    for (int r = 0; r < 16; r++) {
        float mv = v[0]; int mi = id[0];
        #pragma unroll
        for (int o = 16; o; o >>= 1) {
            float ov = __shfl_xor_sync(0xffffffffu, mv, o);
            int   oi = __shfl_xor_sync(0xffffffffu, mi, o);
            if (ov < mv || (ov == mv && oi < mi)) { mv = ov; mi = oi; }
        }
        if (lane == 0) { s_lv[w * 16 + r] = mv; s_li[w * 16 + r] = mi; }
        if (id[0] == mi) {
            #pragma unroll
            for (int k = 0; k < 15; k++) { v[k] = v[k+1]; id[k] = id[k+1]; }
            v[15] = 3.4e38f; id[15] = 0x7fffffff;
        }
    }
    __syncthreads();

    // Phase 2b: warp 0 merges the 8 sorted 16-lists into the global top-16
    __shared__ int cand[16];
    if (tid < 32) {
        int pos = 0;
        #pragma unroll 1
        for (int k = 0; k < 16; k++) {
            float hv = (lane < 8 && pos < 16) ? s_lv[lane * 16 + pos] : 3.4e38f;
            int   hi = (lane < 8 && pos < 16) ? s_li[lane * 16 + pos] : 0x7fffffff;
            float bv = hv; int bi = hi;
            #pragma unroll
            for (int o = 16; o; o >>= 1) {
                float ov = __shfl_xor_sync(0xffffffffu, bv, o);
                int   oi = __shfl_xor_sync(0xffffffffu, bi, o);
                if (ov < bv || (ov == bv && oi < bi)) { bv = ov; bi = oi; }
            }
            if (lane == 0) cand[k] = bi;
            if (hi == bi) pos++;   // unique ids -> exactly the owning lane advances
        }
    }
    __syncthreads();

    // exact fp32 rescore of 16 candidates (8 warps x 2 candidates)
    __shared__ float dex[16];
    const float* srow = src + (size_t)n * DD_;
    for (int c = w; c < 16; c += 8) {
        int m = cand[c];
        const float* a = anchors + (size_t)m * DD_;
        float s = 0.f;
        for (int i = lane; i < DD_; i += 32) s += srow[i] * a[i];
        #pragma unroll
        for (int o = 16; o; o >>= 1) s += __shfl_xor_sync(0xffffffffu, s, o);
        if (lane == 0) dex[c] = g_anorm[m] - 2.0f * s;
    }
    __syncthreads();

    __shared__ int win5[5];
    if (tid == 0) {
        bool used[16];
        #pragma unroll
        for (int i = 0; i < 16; i++) used[i] = false;
        for (int r2 = 0; r2 < 5; r2++) {
            float bv = 3.4e38f; int bi = 0x7fffffff; int bc = 0;
            for (int c = 0; c < 16; c++) {
                if (used[c]) continue;
                if (dex[c] < bv || (dex[c] == bv && cand[c] < bi)) {
                    bv = dex[c]; bi = cand[c]; bc = c;
                }
            }
            used[bc] = true; win5[r2] = bi;
        }
    }
    __syncthreads();

    // neigh mean -> split bf16
    for (int c = tid; c < DD_; c += 256) {
        float s = 0.f;
        #pragma unroll
        for (int k = 0; k < 5; k++) s += anchors[(size_t)win5[k] * DD_ + c];
        float m = s * 0.2f;
        __nv_bfloat16 h = __float2bfloat16(m);
        __nv_bfloat16 l = __float2bfloat16(m - __bfloat162float(h));
        g_neigh_hi[(size_t)n * DD_ + c] = h;
        g_neigh_lo[(size_t)n * DD_ + c] = l;
    }
}

// ---------------- BN: deterministic two-stage column stats ----------------
__global__ __launch_bounds__(256) void bn_stats_kernel(const float* __restrict__ X) {
    int b = blockIdx.x;
    int c0 = threadIdx.x, c1 = threadIdx.x + 256;
    float s0 = 0, q0 = 0, s1 = 0, q1 = 0;
    const float* p = X + (size_t)b * 128 * DD_;
    for (int r = 0; r < 128; r++) {
        float x0 = p[(size_t)r * DD_ + c0];
        float x1 = p[(size_t)r * DD_ + c1];
        s0 += x0; q0 += x0 * x0;
        s1 += x1; q1 += x1 * x1;
    }
    g_part[b * DD_ + c0] = s0;
    g_part[b * DD_ + c1] = s1;
    g_part[128 * DD_ + b * DD_ + c0] = q0;
    g_part[128 * DD_ + b * DD_ + c1] = q1;
}

__global__ void bn_finalize_kernel(const float* __restrict__ g,
                                   const float* __restrict__ bt) {
    int c = blockIdx.x * 256 + threadIdx.x;
    float s = 0, q = 0;
    for (int b = 0; b < 128; b++) {
        s += g_part[b * DD_ + c];
        q += g_part[128 * DD_ + b * DD_ + c];
    }
    float mu = s * (1.0f / NN_);
    float var = q * (1.0f / NN_) - mu * mu;
    float sc = g[c] * rsqrtf(var + 1e-5f);
    g_scale[c] = sc;
    g_shift[c] = bt[c] - mu * sc;
}

// BN apply; SPLIT: also emit hi/lo bf16 (same linear layout, ld=512)
template <bool TANH, bool SPLIT>
__global__ void bn_apply_kernel(const float* __restrict__ X, float* __restrict__ Y,
                                __nv_bfloat16* __restrict__ Yhi,
                                __nv_bfloat16* __restrict__ Ylo) {
    size_t i = ((size_t)blockIdx.x * 256 + threadIdx.x) * 4;
    int c = (int)(i & (DD_ - 1));
    float4 x  = *reinterpret_cast<const float4*>(X + i);
    float4 sc = *reinterpret_cast<const float4*>(g_scale + c);
    float4 sh = *reinterpret_cast<const float4*>(g_shift + c);
    float4 y;
    y.x = x.x * sc.x + sh.x; y.y = x.y * sc.y + sh.y;
    y.z = x.z * sc.z + sh.z; y.w = x.w * sc.w + sh.w;
    if (TANH) { y.x = tanhf(y.x); y.y = tanhf(y.y); y.z = tanhf(y.z); y.w = tanhf(y.w); }
    *reinterpret_cast<float4*>(Y + i) = y;
    if (SPLIT) {
        __nv_bfloat162 h0, l0, h1, l1;
        split2(y.x, y.y, h0, l0);
        split2(y.z, y.w, h1, l1);
        uint2 ph, pl;
        ph.x = *reinterpret_cast<unsigned*>(&h0); ph.y = *reinterpret_cast<unsigned*>(&h1);
        pl.x = *reinterpret_cast<unsigned*>(&l0); pl.y = *reinterpret_cast<unsigned*>(&l1);
        *reinterpret_cast<uint2*>(Yhi + i) = ph;
        *reinterpret_cast<uint2*>(Ylo + i) = pl;
    }
}

// ---------------- launch ----------------
static float* symAddr(const void* symbol) {
    void* p = nullptr;
    cudaGetSymbolAddress(&p, symbol);
    return (float*)p;
}

extern "C" void kernel_launch(void* const* d_in, const int* in_sizes, int n_in,
                              void* d_out, int out_size) {
    (void)in_sizes; (void)n_in; (void)out_size;
    const float* src    = (const float*)d_in[0];
    const float* anchor = (const float*)d_in[1];
    const float* W_dim  = (const float*)d_in[2];
    const float* b_dim  = (const float*)d_in[3];
    const float* W_fus  = (const float*)d_in[4];
    const float* b_fus  = (const float*)d_in[5];
    const float* W_e1   = (const float*)d_in[6];
    const float* b_e1   = (const float*)d_in[7];
    const float* W_e2   = (const float*)d_in[8];
    const float* b_e2   = (const float*)d_in[9];
    const float* g1     = (const float*)d_in[10];
    const float* bt1    = (const float*)d_in[11];
    const float* g2     = (const float*)d_in[12];
    const float* bt2    = (const float*)d_in[13];
    const float* W_d    = (const float*)d_in[14];
    const float* b_d    = (const float*)d_in[15];
    const float* g_d    = (const float*)d_in[16];
    const float* bt_d   = (const float*)d_in[17];
    float* out = (float*)d_out;

    float* pComb   = symAddr(g_comb);
    float* pCombn  = symAddr(g_combn);
    float* pR      = symAddr(g_r);
    float* pDec    = symAddr(g_dec);
    __nv_bfloat16* pSbf     = (__nv_bfloat16*)symAddr(g_S_bf);
    __nv_bfloat16* pAnchBf  = (__nv_bfloat16*)symAddr(g_anch_bf);
    __nv_bfloat16* pNeighH  = (__nv_bfloat16*)symAddr(g_neigh_hi);
    __nv_bfloat16* pNeighL  = (__nv_bfloat16*)symAddr(g_neigh_lo);
    __nv_bfloat16* pCatH    = (__nv_bfloat16*)symAddr(g_cat_hi);
    __nv_bfloat16* pCatL    = (__nv_bfloat16*)symAddr(g_cat_lo);
    __nv_bfloat16* pCombnH  = (__nv_bfloat16*)symAddr(g_combn_hi);
    __nv_bfloat16* pCombnL  = (__nv_bfloat16*)symAddr(g_combn_lo);
    __nv_bfloat16* pHH      = (__nv_bfloat16*)symAddr(g_h_hi);
    __nv_bfloat16* pHL      = (__nv_bfloat16*)symAddr(g_h_lo);
    __nv_bfloat16* pC2H     = (__nv_bfloat16*)symAddr(g_c2_hi);
    __nv_bfloat16* pC2L     = (__nv_bfloat16*)symAddr(g_c2_lo);
    __nv_bfloat16* pWdimH   = (__nv_bfloat16*)symAddr(g_WdimT_hi);
    __nv_bfloat16* pWdimL   = (__nv_bfloat16*)symAddr(g_WdimT_lo);
    __nv_bfloat16* pWfusH   = (__nv_bfloat16*)symAddr(g_WfusT_hi);
    __nv_bfloat16* pWfusL   = (__nv_bfloat16*)symAddr(g_WfusT_lo);
    __nv_bfloat16* pWe1H    = (__nv_bfloat16*)symAddr(g_We1T_hi);
    __nv_bfloat16* pWe1L    = (__nv_bfloat16*)symAddr(g_We1T_lo);
    __nv_bfloat16* pWe2H    = (__nv_bfloat16*)symAddr(g_We2T_hi);
    __nv_bfloat16* pWe2L    = (__nv_bfloat16*)symAddr(g_We2T_lo);
    __nv_bfloat16* pWdH     = (__nv_bfloat16*)symAddr(g_WdT_hi);
    __nv_bfloat16* pWdL     = (__nv_bfloat16*)symAddr(g_WdT_lo);

    const int T = 256;
    const int SM = GEMM_SMEM;   // 61440 bytes dynamic smem per GEMM block

    // Opt-in to >48KB dynamic smem for every GEMM instantiation (idempotent).
    cudaFuncSetAttribute(gemm_bf16_mp<1, 5>, cudaFuncAttributeMaxDynamicSharedMemorySize, SM);
    cudaFuncSetAttribute(gemm_bf16_mp<3, 4>, cudaFuncAttributeMaxDynamicSharedMemorySize, SM);
    cudaFuncSetAttribute(gemm_bf16_mp<3, 1>, cudaFuncAttributeMaxDynamicSharedMemorySize, SM);
    cudaFuncSetAttribute(gemm_bf16_mp<3, 2>, cudaFuncAttributeMaxDynamicSharedMemorySize, SM);
    cudaFuncSetAttribute(gemm_bf16_mp<3, 3>, cudaFuncAttributeMaxDynamicSharedMemorySize, SM);

    // 0) anchors -> bf16
    tobf16_kernel<<<(MM_ * DD_ / 4) / T, T>>>(anchor, pAnchBf);
    // 1) src -> split bf16 into cat (cat_hi left half == bf16(src), reused below)
    pack_split_kernel<<<(NN_ * DD_ / 4) / T, T>>>(src);
    // 2) anchor norms (fp32)
    anorm_kernel<<<MM_ / 8, T>>>(anchor);
    // 3) coarse S = bf16(src) @ anchor_bf^T -> bf16 store (A = cat_hi left, lda=1024)
    gemm_bf16_mp<1, 5><<<dim3(MM_ / 128, NN_ / 128), T, SM>>>(
        pCatH, nullptr, pAnchBf, nullptr, nullptr, nullptr,
        nullptr, pSbf, nullptr, DD_, 2 * DD_, DD_, MM_);
    // 4) one weight split
    tsplit_kernel<<<dim3(DD_ / 32, DD_ / 32), dim3(32, 8)>>>(W_dim, pWdimH, pWdimL, DD_, DD_);
    // 5) top-16 -> exact rescore -> top-5 -> neigh (split bf16)
    topk16_kernel<<<NN_, T>>>(src, anchor);

    // remaining weight splits
    tsplit_kernel<<<dim3(DD_ / 32, 2 * DD_ / 32), dim3(32, 8)>>>(W_fus, pWfusH, pWfusL, 2 * DD_, DD_);
    tsplit_kernel<<<dim3(FF_ / 32, DD_ / 32), dim3(32, 8)>>>(W_e1, pWe1H, pWe1L, DD_, FF_);
    tsplit_kernel<<<dim3(DD_ / 32, FF_ / 32), dim3(32, 8)>>>(W_e2, pWe2H, pWe2L, FF_, DD_);
    tsplit_kernel<<<dim3(DD_ / 32, DD_ / 32), dim3(32, 8)>>>(W_d, pWdH, pWdL, DD_, DD_);

    // cat right = neigh @ W_dim + b_dim (split epilogue)
    gemm_bf16_mp<3, 4><<<dim3(DD_ / 128, NN_ / 128), T, SM>>>(
        pNeighH, pNeighL, pWdimH, pWdimL, b_dim, nullptr,
        nullptr, pCatH + DD_, pCatL + DD_, DD_, DD_, DD_, 2 * DD_);

    // comb = cat @ W_fus + b_fus (K=1024) -> fp32
    gemm_bf16_mp<3, 1><<<dim3(DD_ / 128, NN_ / 128), T, SM>>>(
        pCatH, pCatL, pWfusH, pWfusL, b_fus, nullptr,
        pComb, nullptr, nullptr, 2 * DD_, 2 * DD_, 2 * DD_, DD_);

    // BN1 -> combn fp32 + split bf16
    bn_stats_kernel<<<128, T>>>(pComb);
    bn_finalize_kernel<<<2, T>>>(g1, bt1);
    bn_apply_kernel<false, true><<<(NN_ * DD_ / 4) / T, T>>>(pComb, pCombn, pCombnH, pCombnL);

    // h = tanh(combn @ W_e1 + b_e1) -> split bf16 directly (no fp32 h)
    gemm_bf16_mp<3, 2><<<dim3(FF_ / 128, NN_ / 128), T, SM>>>(
        pCombnH, pCombnL, pWe1H, pWe1L, b_e1, nullptr,
        nullptr, pHH, pHL, DD_, DD_, DD_, FF_);

    // r = combn + (h @ W_e2 + b_e2) (K=2048) -> fp32
    gemm_bf16_mp<3, 3><<<dim3(DD_ / 128, NN_ / 128), T, SM>>>(
        pHH, pHL, pWe2H, pWe2L, b_e2, pCombn,
        pR, nullptr, nullptr, FF_, FF_, FF_, DD_);

    // BN2 -> comb2 split bf16
    bn_stats_kernel<<<128, T>>>(pR);
    bn_finalize_kernel<<<2, T>>>(g2, bt2);
    bn_apply_kernel<false, true><<<(NN_ * DD_ / 4) / T, T>>>(pR, pComb, pC2H, pC2L);

    // dec = comb2 @ W_d + b_d -> fp32
    gemm_bf16_mp<3, 1><<<dim3(DD_ / 128, NN_ / 128), T, SM>>>(
        pC2H, pC2L, pWdH, pWdL, b_d, nullptr,
        pDec, nullptr, nullptr, DD_, DD_, DD_, DD_);

    // out = tanh(BN(dec))
    bn_stats_kernel<<<128, T>>>(pDec);
    bn_finalize_kernel<<<2, T>>>(g_d, bt_d);
    bn_apply_kernel<true, false><<<(NN_ * DD_ / 4) / T, T>>>(pDec, out, nullptr, nullptr);
}